// round 13
// baseline (speedup 1.0000x reference)
#include <cuda_runtime.h>
#include <cuda_bf16.h>
#include <cstdint>
#include <math.h>

// Problem constants (fixed by the dataset)
#define LEN    21760
#define BATCH  2
#define MTOK   (BATCH * LEN)          // 43520
#define DMODEL 256
#define DFFN   1024
#define NHEADS 8
#define LNEPS  1e-5f

typedef __nv_bfloat16 bf16;
typedef __nv_bfloat162 bf162;

// ---------------------------------------------------------------------------
// Scratch (device globals — no allocation)
// ---------------------------------------------------------------------------
__device__ bf16  g_srcb [(size_t)MTOK * DMODEL];
__device__ bf16  g_qb   [(size_t)MTOK * DMODEL];
__device__ bf16  g_value[(size_t)MTOK * DMODEL];
__device__ float g_off  [(size_t)MTOK * DMODEL];
__device__ float g_attn [(size_t)MTOK * 128];
__device__ bf16  g_samp [(size_t)MTOK * DMODEL];
__device__ float g_x    [(size_t)MTOK * DMODEL];
__device__ bf16  g_xb   [(size_t)MTOK * DMODEL];
__device__ bf16  g_h    [(size_t)MTOK * DFFN];
// transposed bf16 weights [N, K] (K-major)
__device__ bf16 g_wtval   [256 * 256];
__device__ bf16 g_wtoffat [384 * 256];    // rows 0-255: w_off; 256-383: w_attn
__device__ bf16 g_wtout   [256 * 256];
__device__ bf16 g_wt1     [1024 * 256];
__device__ bf16 g_wt2     [256 * 1024];

// ---------------------------------------------------------------------------
// Helpers
// ---------------------------------------------------------------------------
__device__ __forceinline__ uint32_t smem_u32(const void* p) {
    uint32_t a;
    asm("{ .reg .u64 t; cvta.to.shared.u64 t, %1; cvt.u32.u64 %0, t; }" : "=r"(a) : "l"(p));
    return a;
}
__device__ __forceinline__ void cp_async16(uint32_t saddr, const void* gaddr) {
    asm volatile("cp.async.cg.shared.global [%0], [%1], 16;" :: "r"(saddr), "l"(gaddr));
}
__device__ __forceinline__ void cp_commit() { asm volatile("cp.async.commit_group;"); }

__device__ __forceinline__ void mma_bf16(float* d, const uint32_t* a, const uint32_t* b) {
    asm volatile(
        "mma.sync.aligned.m16n8k16.row.col.f32.bf16.bf16.f32 "
        "{%0,%1,%2,%3}, {%4,%5,%6,%7}, {%8,%9}, {%0,%1,%2,%3};"
        : "+f"(d[0]), "+f"(d[1]), "+f"(d[2]), "+f"(d[3])
        : "r"(a[0]), "r"(a[1]), "r"(a[2]), "r"(a[3]), "r"(b[0]), "r"(b[1]));
}

// ---------------------------------------------------------------------------
// prep: srcb = bf16(src), qb = bf16(src + pos)
// ---------------------------------------------------------------------------
__global__ __launch_bounds__(256)
void prep_kernel(const float* __restrict__ src, const float* __restrict__ pos,
                 bf16* __restrict__ srcb, bf16* __restrict__ qb, int n4)
{
    const int i = blockIdx.x * blockDim.x + threadIdx.x;
    if (i >= n4) return;
    float4 s = ((const float4*)src)[i];
    float4 p = ((const float4*)pos)[i];
    bf162* sb = (bf162*)srcb + i * 2;
    bf162* qo = (bf162*)qb + i * 2;
    sb[0] = __floats2bfloat162_rn(s.x, s.y);
    sb[1] = __floats2bfloat162_rn(s.z, s.w);
    qo[0] = __floats2bfloat162_rn(s.x + p.x, s.y + p.y);
    qo[1] = __floats2bfloat162_rn(s.z + p.z, s.w + p.w);
}

// ---------------------------------------------------------------------------
// All weight transposes in ONE launch. out[(rowOff+n)*K + k] = bf16(in[k*N+n])
// ---------------------------------------------------------------------------
struct TSeg { const float* in; bf16* out; int K, N, start, rowOff; };

__global__ void transpose_all(TSeg s0, TSeg s1, TSeg s2, TSeg s3, TSeg s4, TSeg s5)
{
    TSeg s;
    const int b = blockIdx.x;
    if      (b < s1.start) s = s0;
    else if (b < s2.start) s = s1;
    else if (b < s3.start) s = s2;
    else if (b < s4.start) s = s3;
    else if (b < s5.start) s = s4;
    else                   s = s5;

    const int local = b - s.start;
    const int tx_n  = s.N / 32;
    const int n0 = (local % tx_n) * 32;
    const int k0 = (local / tx_n) * 32;

    __shared__ float t[32][33];
    const int tx = threadIdx.x, ty = threadIdx.y;
#pragma unroll
    for (int j = 0; j < 32; j += 8)
        t[ty + j][tx] = s.in[(size_t)(k0 + ty + j) * s.N + n0 + tx];
    __syncthreads();
#pragma unroll
    for (int j = 0; j < 32; j += 8)
        s.out[(size_t)(s.rowOff + n0 + ty + j) * s.K + k0 + tx] = __float2bfloat16(t[tx][ty + j]);
}

// ---------------------------------------------------------------------------
// bf16 mma GEMM.  BM=BN=128, BK=64.  128 threads, 4 warps (2x2), warp 64x64,
// m16n8k16 tiles 4x8 per warp -> 32 LDS : 32 MMA per K-substep.
// Split-output mode: col >= splitCol goes to Cf2 (stride N2) with bias2.
// ---------------------------------------------------------------------------
#define LDT 72
#define TBYTES (128 * LDT * 2)

__global__ __launch_bounds__(128, 2)
void gemm_bf(const bf16* __restrict__ A, const bf16* __restrict__ BT,
             const float* __restrict__ bias, const float* __restrict__ bias2,
             const unsigned char* __restrict__ mask,
             float* __restrict__ Cf, float* __restrict__ Cf2, bf16* __restrict__ Cb,
             int K, int N, int N2, int splitCol, int relu)
{
    extern __shared__ bf16 sm[];
    bf16* As = sm;
    bf16* Bs = sm + 2 * 128 * LDT;

    const int tid  = threadIdx.x;
    const int wid  = tid >> 5;
    const int lane = tid & 31;
    const int gr   = lane >> 2;
    const int gc   = lane & 3;
    const int wm   = wid & 1;          // row half (64)
    const int wn   = wid >> 1;         // col half (64)
    const int row0 = blockIdx.y * 128;
    const int col0 = blockIdx.x * 128;

    float acc[4][8][4];
#pragma unroll
    for (int mt = 0; mt < 4; mt++)
#pragma unroll
        for (int nt = 0; nt < 8; nt++)
#pragma unroll
            for (int r = 0; r < 4; r++) acc[mt][nt][r] = 0.f;

    const uint32_t sA = smem_u32(As);
    const uint32_t sB = smem_u32(Bs);

    const int nch = K >> 6;
    const int lrow = tid >> 3;          // 0..15
    const int lc   = (tid & 7) << 3;

    const bf16* Ab = A  + (size_t)(row0 + lrow) * K + lc;
    const bf16* Bb = BT + (size_t)(col0 + lrow) * K + lc;

#define LOAD_CHUNK(i) do {                                                        \
        const int _k0 = (i) << 6;                                                 \
        const uint32_t _abase = sA + ((i) & 1) * TBYTES;                          \
        const uint32_t _bbase = sB + ((i) & 1) * TBYTES;                          \
        _Pragma("unroll")                                                         \
        for (int it = 0; it < 8; it++) {                                          \
            const int r = it * 16;                                                \
            cp_async16(_abase + (uint32_t)(((lrow + r) * LDT + lc) * 2),          \
                       Ab + (size_t)r * K + _k0);                                 \
            cp_async16(_bbase + (uint32_t)(((lrow + r) * LDT + lc) * 2),          \
                       Bb + (size_t)r * K + _k0);                                 \
        }                                                                         \
        cp_commit();                                                              \
    } while (0)

    LOAD_CHUNK(0);

    for (int i = 0; i < nch; i++) {
        if (i + 1 < nch) {
            LOAD_CHUNK(i + 1);
            asm volatile("cp.async.wait_group 1;" ::: "memory");
        } else {
            asm volatile("cp.async.wait_group 0;" ::: "memory");
        }
        __syncthreads();

        const bf16* Ac = As + (i & 1) * (128 * LDT);
        const bf16* Bc = Bs + (i & 1) * (128 * LDT);

#pragma unroll
        for (int ks = 0; ks < 4; ks++) {
            const int kk = ks * 16;
            uint32_t af[4][4];
#pragma unroll
            for (int mt = 0; mt < 4; mt++) {
                const int r = wm * 64 + mt * 16 + gr;
                af[mt][0] = *(const uint32_t*)&Ac[(r)     * LDT + kk + 2 * gc];
                af[mt][1] = *(const uint32_t*)&Ac[(r + 8) * LDT + kk + 2 * gc];
                af[mt][2] = *(const uint32_t*)&Ac[(r)     * LDT + kk + 8 + 2 * gc];
                af[mt][3] = *(const uint32_t*)&Ac[(r + 8) * LDT + kk + 8 + 2 * gc];
            }
            uint32_t bfr[8][2];
#pragma unroll
            for (int nt = 0; nt < 8; nt++) {
                const int r = wn * 64 + nt * 8 + gr;
                bfr[nt][0] = *(const uint32_t*)&Bc[r * LDT + kk + 2 * gc];
                bfr[nt][1] = *(const uint32_t*)&Bc[r * LDT + kk + 8 + 2 * gc];
            }
#pragma unroll
            for (int mt = 0; mt < 4; mt++)
#pragma unroll
                for (int nt = 0; nt < 8; nt++)
                    mma_bf16(acc[mt][nt], af[mt], bfr[nt]);
        }
        __syncthreads();
    }

    const bool second = (splitCol >= 0) && (col0 >= splitCol);
    const float* biasP = second ? bias2 : bias;
    float* CfP = second ? Cf2 : Cf;
    const int  Nout  = second ? N2 : N;
    const int  cbase = second ? col0 - splitCol : col0;

#pragma unroll
    for (int mt = 0; mt < 4; mt++) {
        const int r0 = row0 + wm * 64 + mt * 16 + gr;
        const bool m0 = mask && mask[r0];
        const bool m1 = mask && mask[r0 + 8];
#pragma unroll
        for (int nt = 0; nt < 8; nt++) {
            const int col = cbase + wn * 64 + nt * 8 + gc * 2;
            const float b0 = __ldg(biasP + col);
            const float b1 = __ldg(biasP + col + 1);
            float v0 = acc[mt][nt][0] + b0, v1 = acc[mt][nt][1] + b1;
            float v2 = acc[mt][nt][2] + b0, v3 = acc[mt][nt][3] + b1;
            if (relu) {
                v0 = fmaxf(v0, 0.f); v1 = fmaxf(v1, 0.f);
                v2 = fmaxf(v2, 0.f); v3 = fmaxf(v3, 0.f);
            }
            if (m0) { v0 = v1 = 0.f; }
            if (m1) { v2 = v3 = 0.f; }
            if (CfP) {
                *(float2*)(CfP + (size_t)r0 * Nout + col)       = make_float2(v0, v1);
                *(float2*)(CfP + (size_t)(r0 + 8) * Nout + col) = make_float2(v2, v3);
            }
            if (Cb) {
                *(bf162*)(Cb + (size_t)r0 * Nout + col)       = __floats2bfloat162_rn(v0, v1);
                *(bf162*)(Cb + (size_t)(r0 + 8) * Nout + col) = __floats2bfloat162_rn(v2, v3);
            }
        }
    }
}

// ---------------------------------------------------------------------------
// GEMM + bias + residual + LayerNorm fused.  N = 256 (full row per CTA).
// BM=128, BN=256, 256 threads (8 warps 2x4), warp tile 64x64 (proven shape),
// m16n8k16 tiles 4x8 per warp -> 32 LDS : 32 MMA per K-substep.
// ---------------------------------------------------------------------------
__global__ __launch_bounds__(256, 1)
void gemm_ln(const bf16* __restrict__ A, const bf16* __restrict__ BT,
             const float* __restrict__ bias, const float* __restrict__ res,
             const float* __restrict__ lng, const float* __restrict__ lnb,
             float* __restrict__ Of, bf16* __restrict__ Ob, int K)
{
    extern __shared__ bf16 sm[];
    bf16* As = sm;                       // [2][128][72]
    bf16* Bs = sm + 2 * 128 * LDT;       // [2][256][72]

    const int tid  = threadIdx.x;
    const int wid  = tid >> 5;
    const int lane = tid & 31;
    const int gr   = lane >> 2;
    const int gc   = lane & 3;
    const int wm   = wid & 1;            // row half (64)
    const int wn   = wid >> 1;           // col quarter (64)
    const int row0 = blockIdx.y * 128;

    const uint32_t sA = smem_u32(As);
    const uint32_t sB = smem_u32(Bs);

    float acc[4][8][4];
#pragma unroll
    for (int mt = 0; mt < 4; mt++)
#pragma unroll
        for (int nt = 0; nt < 8; nt++)
#pragma unroll
            for (int r = 0; r < 4; r++) acc[mt][nt][r] = 0.f;

    const int nch = K >> 6;
    const int lrow = tid >> 3;           // 0..31
    const int lc   = (tid & 7) << 3;

#define LN_LOAD(i) do {                                                            \
        const int _k0 = (i) << 6;                                                  \
        const uint32_t _ab = sA + ((i) & 1) * TBYTES;                              \
        const uint32_t _bb = sB + ((i) & 1) * (256 * LDT * 2);                     \
        _Pragma("unroll")                                                          \
        for (int it = 0; it < 4; it++) {                                           \
            const int r = lrow + it * 32;                                          \
            cp_async16(_ab + (uint32_t)((r * LDT + lc) * 2),                       \
                       A + (size_t)(row0 + r) * K + lc + _k0);                     \
        }                                                                          \
        _Pragma("unroll")                                                          \
        for (int it = 0; it < 8; it++) {                                           \
            const int r = lrow + it * 32;                                          \
            cp_async16(_bb + (uint32_t)((r * LDT + lc) * 2),                       \
                       BT + (size_t)r * K + lc + _k0);                             \
        }                                                                          \
        cp_commit();                                                               \
    } while (0)

    LN_LOAD(0);

    for (int i = 0; i < nch; i++) {
        if (i + 1 < nch) {
            LN_LOAD(i + 1);
            asm volatile("cp.async.wait_group 1;" ::: "memory");
        } else {
            asm volatile("cp.async.wait_group 0;" ::: "memory");
        }
        __syncthreads();

        const bf16* Ac = As + (i & 1) * (128 * LDT);
        const bf16* Bc = Bs + (i & 1) * (256 * LDT);

#pragma unroll
        for (int ks = 0; ks < 4; ks++) {
            const int kk = ks * 16;
            uint32_t af[4][4];
#pragma unroll
            for (int mt = 0; mt < 4; mt++) {
                const int r = wm * 64 + mt * 16 + gr;
                af[mt][0] = *(const uint32_t*)&Ac[(r)     * LDT + kk + 2 * gc];
                af[mt][1] = *(const uint32_t*)&Ac[(r + 8) * LDT + kk + 2 * gc];
                af[mt][2] = *(const uint32_t*)&Ac[(r)     * LDT + kk + 8 + 2 * gc];
                af[mt][3] = *(const uint32_t*)&Ac[(r + 8) * LDT + kk + 8 + 2 * gc];
            }
            uint32_t bfr[8][2];
#pragma unroll
            for (int nt = 0; nt < 8; nt++) {
                const int r = wn * 64 + nt * 8 + gr;
                bfr[nt][0] = *(const uint32_t*)&Bc[r * LDT + kk + 2 * gc];
                bfr[nt][1] = *(const uint32_t*)&Bc[r * LDT + kk + 8 + 2 * gc];
            }
#pragma unroll
            for (int mt = 0; mt < 4; mt++)
#pragma unroll
                for (int nt = 0; nt < 8; nt++)
                    mma_bf16(acc[mt][nt], af[mt], bfr[nt]);
        }
        __syncthreads();
    }

    // ---- fused bias + residual + LayerNorm ----
    // Each row (128 local) covered by 4 warps (same wm, wn=0..3), 64 cols each.
    float2* sred = (float2*)sm;          // [128][4] partials

#pragma unroll
    for (int mt = 0; mt < 4; mt++) {
        const int rA = wm * 64 + mt * 16 + gr;
        const int rB = rA + 8;
        float sA2 = 0.f, qA = 0.f, sB2 = 0.f, qB = 0.f;
#pragma unroll
        for (int nt = 0; nt < 8; nt++) {
            const int col = wn * 64 + nt * 8 + gc * 2;
            const float b0 = __ldg(bias + col);
            const float b1 = __ldg(bias + col + 1);
            const float2 rs0 = *(const float2*)(res + (size_t)(row0 + rA) * 256 + col);
            const float2 rs1 = *(const float2*)(res + (size_t)(row0 + rB) * 256 + col);
            acc[mt][nt][0] += b0 + rs0.x;
            acc[mt][nt][1] += b1 + rs0.y;
            acc[mt][nt][2] += b0 + rs1.x;
            acc[mt][nt][3] += b1 + rs1.y;
            sA2 += acc[mt][nt][0] + acc[mt][nt][1];
            qA  += acc[mt][nt][0] * acc[mt][nt][0] + acc[mt][nt][1] * acc[mt][nt][1];
            sB2 += acc[mt][nt][2] + acc[mt][nt][3];
            qB  += acc[mt][nt][2] * acc[mt][nt][2] + acc[mt][nt][3] * acc[mt][nt][3];
        }
#pragma unroll
        for (int o = 1; o <= 2; o <<= 1) {
            sA2 += __shfl_xor_sync(0xffffffffu, sA2, o);
            qA  += __shfl_xor_sync(0xffffffffu, qA,  o);
            sB2 += __shfl_xor_sync(0xffffffffu, sB2, o);
            qB  += __shfl_xor_sync(0xffffffffu, qB,  o);
        }
        if (gc == 0) {
            sred[rA * 4 + wn] = make_float2(sA2, qA);
            sred[rB * 4 + wn] = make_float2(sB2, qB);
        }
    }
    __syncthreads();

#pragma unroll
    for (int mt = 0; mt < 4; mt++) {
        const int rA = wm * 64 + mt * 16 + gr;
        const int rB = rA + 8;
        float2 pA = make_float2(0.f, 0.f), pB = make_float2(0.f, 0.f);
#pragma unroll
        for (int w = 0; w < 4; w++) {
            float2 a = sred[rA * 4 + w]; pA.x += a.x; pA.y += a.y;
            float2 b = sred[rB * 4 + w]; pB.x += b.x; pB.y += b.y;
        }
        const float mA = pA.x * (1.f / 256.f);
        const float vA = fmaxf(pA.y * (1.f / 256.f) - mA * mA, 0.f);
        const float rAst = rsqrtf(vA + LNEPS);
        const float mB = pB.x * (1.f / 256.f);
        const float vB = fmaxf(pB.y * (1.f / 256.f) - mB * mB, 0.f);
        const float rBst = rsqrtf(vB + LNEPS);

#pragma unroll
        for (int nt = 0; nt < 8; nt++) {
            const int col = wn * 64 + nt * 8 + gc * 2;
            const float g0 = __ldg(lng + col),  g1 = __ldg(lng + col + 1);
            const float e0 = __ldg(lnb + col),  e1 = __ldg(lnb + col + 1);
            const float o0 = (acc[mt][nt][0] - mA) * rAst * g0 + e0;
            const float o1 = (acc[mt][nt][1] - mA) * rAst * g1 + e1;
            const float o2 = (acc[mt][nt][2] - mB) * rBst * g0 + e0;
            const float o3 = (acc[mt][nt][3] - mB) * rBst * g1 + e1;
            *(float2*)(Of + (size_t)(row0 + rA) * 256 + col) = make_float2(o0, o1);
            *(float2*)(Of + (size_t)(row0 + rB) * 256 + col) = make_float2(o2, o3);
            if (Ob) {
                *(bf162*)(Ob + (size_t)(row0 + rA) * 256 + col) = __floats2bfloat162_rn(o0, o1);
                *(bf162*)(Ob + (size_t)(row0 + rB) * 256 + col) = __floats2bfloat162_rn(o2, o3);
            }
        }
    }
}

// ---------------------------------------------------------------------------
// Deformable-attention sampling.  One warp per (token, head).
// lane = pgrp*8 + cq: pgrp (0..3) = point within level, cq (0..7) = channel
// quad (4 channels, uint2).  All 4 points of a level processed concurrently;
// each corner gather is an 8-lane 64B coalesced request.
// ---------------------------------------------------------------------------
__global__ __launch_bounds__(256)
void samp_kernel(const bf16* __restrict__ value, const float* __restrict__ attn,
                 const float* __restrict__ off,  const float* __restrict__ ref,
                 bf16* __restrict__ out)
{
    const int gw   = (blockIdx.x * blockDim.x + threadIdx.x) >> 5;
    const int lane = threadIdx.x & 31;
    if (gw >= MTOK * NHEADS) return;

    const int h    = gw & 7;
    const int bl   = gw >> 3;
    const int b    = (bl >= LEN) ? 1 : 0;
    const int pgrp = lane >> 3;          // point within level
    const int cq   = lane & 7;           // channel quad

    // softmax across lanes (lanes 0..15 hold the 16 logits)
    float logit = (lane < 16) ? __ldg(attn + bl * 128 + h * 16 + lane) : -1e30f;
    float m = logit;
#pragma unroll
    for (int o = 16; o > 0; o >>= 1) m = fmaxf(m, __shfl_xor_sync(0xffffffffu, m, o));
    float e = (lane < 16) ? __expf(logit - m) : 0.f;
    float s = e;
#pragma unroll
    for (int o = 16; o > 0; o >>= 1) s += __shfl_xor_sync(0xffffffffu, s, o);
    const float wn = e / s;

    const float ov = __ldg(off + bl * 256 + h * 32 + lane);   // 32 offsets
    const float rv = (lane < 8) ? __ldg(ref + bl * 8 + lane) : 0.f;

    const int Hs[4] = {128, 64, 32, 16};
    const int Ss[4] = {0, 16384, 20480, 21504};

    float4 acc4 = make_float4(0.f, 0.f, 0.f, 0.f);
#pragma unroll
    for (int l = 0; l < 4; l++) {
        const int   Wl = Hs[l];
        const float fW = (float)Wl;
        const float rx = __shfl_sync(0xffffffffu, rv, 2 * l);
        const float ry = __shfl_sync(0xffffffffu, rv, 2 * l + 1);
        const uint2* vb = (const uint2*)(value + (size_t)(b * LEN + Ss[l]) * 256 + h * 32) + cq;

        const float ox = __shfl_sync(0xffffffffu, ov, l * 8 + pgrp * 2);
        const float oy = __shfl_sync(0xffffffffu, ov, l * 8 + pgrp * 2 + 1);
        const float aw = __shfl_sync(0xffffffffu, wn, l * 4 + pgrp);
        const float x  = fmaf(rx, fW, ox) - 0.5f;
        const float y  = fmaf(ry, fW, oy) - 0.5f;
        const float x0f = floorf(x), y0f = floorf(y);
        const float dx = x - x0f, dy = y - y0f;
        const int   x0 = (int)x0f, y0 = (int)y0f;

        float4 psum = make_float4(0.f, 0.f, 0.f, 0.f);
#pragma unroll
        for (int c = 0; c < 4; c++) {
            const int xi = x0 + (c & 1);
            const int yi = y0 + (c >> 1);
            const float cw = ((c & 1) ? dx : 1.f - dx) * ((c >> 1) ? dy : 1.f - dy);
            const bool valid = (xi >= 0) & (xi < Wl) & (yi >= 0) & (yi < Wl);
            const int xc = min(max(xi, 0), Wl - 1);
            const int yc = min(max(yi, 0), Wl - 1);
            const uint2 raw = vb[(size_t)(yc * Wl + xc) * 64];   // 64 uint2 per 256-bf16 token row
            const float2 v0 = __bfloat1622float2(*(const bf162*)&raw.x);
            const float2 v1 = __bfloat1622float2(*(const bf162*)&raw.y);
            const float w = valid ? cw : 0.f;
            psum.x = fmaf(v0.x, w, psum.x);
            psum.y = fmaf(v0.y, w, psum.y);
            psum.z = fmaf(v1.x, w, psum.z);
            psum.w = fmaf(v1.y, w, psum.w);
        }
        acc4.x = fmaf(aw, psum.x, acc4.x);
        acc4.y = fmaf(aw, psum.y, acc4.y);
        acc4.z = fmaf(aw, psum.z, acc4.z);
        acc4.w = fmaf(aw, psum.w, acc4.w);
    }
    // reduce across the 4 point-groups (lane bits 3,4)
#pragma unroll
    for (int o = 8; o <= 16; o <<= 1) {
        acc4.x += __shfl_xor_sync(0xffffffffu, acc4.x, o);
        acc4.y += __shfl_xor_sync(0xffffffffu, acc4.y, o);
        acc4.z += __shfl_xor_sync(0xffffffffu, acc4.z, o);
        acc4.w += __shfl_xor_sync(0xffffffffu, acc4.w, o);
    }
    if (pgrp == 0) {
        uint2 packed;
        bf162 p0 = __floats2bfloat162_rn(acc4.x, acc4.y);
        bf162 p1 = __floats2bfloat162_rn(acc4.z, acc4.w);
        packed.x = *(const uint32_t*)&p0;
        packed.y = *(const uint32_t*)&p1;
        ((uint2*)(out + (size_t)bl * 256 + h * 32))[cq] = packed;
    }
}

// ---------------------------------------------------------------------------
// Launch
// ---------------------------------------------------------------------------
extern "C" void kernel_launch(void* const* d_in, const int* in_sizes, int n_in,
                              void* d_out, int out_size)
{
    const float* src  = (const float*)d_in[0];
    const float* pos  = (const float*)d_in[1];
    const float* ref  = (const float*)d_in[2];
    const unsigned char* mask = (const unsigned char*)d_in[5];
    const float* w_off  = (const float*)d_in[6];
    const float* b_off  = (const float*)d_in[7];
    const float* w_attn = (const float*)d_in[8];
    const float* b_attn = (const float*)d_in[9];
    const float* w_val  = (const float*)d_in[10];
    const float* b_val  = (const float*)d_in[11];
    const float* w_out  = (const float*)d_in[12];
    const float* b_out  = (const float*)d_in[13];
    const float* ln1g   = (const float*)d_in[14];
    const float* ln1b   = (const float*)d_in[15];
    const float* w1     = (const float*)d_in[16];
    const float* b1     = (const float*)d_in[17];
    const float* w2     = (const float*)d_in[18];
    const float* b2     = (const float*)d_in[19];
    const float* ln2g   = (const float*)d_in[20];
    const float* ln2b   = (const float*)d_in[21];
    float* out = (float*)d_out;

    bf16 *p_srcb, *p_qb, *p_value, *p_samp, *p_xb, *p_h;
    float *p_off, *p_attn, *p_x;
    bf16 *t_val, *t_offat, *t_out, *t_w1, *t_w2;
    cudaGetSymbolAddress((void**)&p_srcb,  g_srcb);
    cudaGetSymbolAddress((void**)&p_qb,    g_qb);
    cudaGetSymbolAddress((void**)&p_value, g_value);
    cudaGetSymbolAddress((void**)&p_off,   g_off);
    cudaGetSymbolAddress((void**)&p_attn,  g_attn);
    cudaGetSymbolAddress((void**)&p_samp,  g_samp);
    cudaGetSymbolAddress((void**)&p_x,     g_x);
    cudaGetSymbolAddress((void**)&p_xb,    g_xb);
    cudaGetSymbolAddress((void**)&p_h,     g_h);
    cudaGetSymbolAddress((void**)&t_val,   g_wtval);
    cudaGetSymbolAddress((void**)&t_offat, g_wtoffat);
    cudaGetSymbolAddress((void**)&t_out,   g_wtout);
    cudaGetSymbolAddress((void**)&t_w1,    g_wt1);
    cudaGetSymbolAddress((void**)&t_w2,    g_wt2);

    const int SMEM   = 2 * 2 * 128 * LDT * 2;                       // 73728
    const int SMEMLN = 2 * (128 + 256) * LDT * 2;                   // 110592
    cudaFuncSetAttribute(gemm_bf, cudaFuncAttributeMaxDynamicSharedMemorySize, SMEM);
    cudaFuncSetAttribute(gemm_ln, cudaFuncAttributeMaxDynamicSharedMemorySize, SMEMLN);

    const int MY = MTOK / 128;   // 340

    // 1. srcb = bf16(src); qb = bf16(src + pos)
    prep_kernel<<<(MTOK * 256 / 4 + 255) / 256, 256>>>(src, pos, p_srcb, p_qb, MTOK * 256 / 4);

    // 2. all weight transposes in one launch
    TSeg s0 = { w_val,  t_val,   256, 256,   0,   0 };
    TSeg s1 = { w_off,  t_offat, 256, 256,  64,   0 };
    TSeg s2 = { w_attn, t_offat, 256, 128, 128, 256 };
    TSeg s3 = { w_out,  t_out,   256, 256, 160,   0 };
    TSeg s4 = { w1,     t_w1,    256, 1024, 224,  0 };
    TSeg s5 = { w2,     t_w2,    1024, 256, 480,  0 };
    transpose_all<<<736, dim3(32, 8)>>>(s0, s1, s2, s3, s4, s5);

    // 3. value = srcb @ w_val + b_val (masked), bf16 out
    gemm_bf<<<dim3(2, MY), 128, SMEM>>>(p_srcb, t_val, b_val, nullptr, mask,
                                        nullptr, nullptr, p_value, 256, 256, 0, -1, 0);
    // 4. [off | attn] = qb @ t_offat  (split epilogue)
    gemm_bf<<<dim3(3, MY), 128, SMEM>>>(p_qb, t_offat, b_off, b_attn, nullptr,
                                        p_off, p_attn, nullptr, 256, 256, 128, 256, 0);
    // 5. deformable sampling
    samp_kernel<<<(MTOK * NHEADS) / 8, 256>>>(p_value, p_attn, p_off, ref, p_samp);
    // 6. x = LN(src + samp @ w_out + b_out)  -> fp32 + bf16
    gemm_ln<<<dim3(1, MY), 256, SMEMLN>>>(p_samp, t_out, b_out, src, ln1g, ln1b, p_x, p_xb, 256);
    // 7. h = relu(xb @ w1 + b1), bf16 out
    gemm_bf<<<dim3(8, MY), 128, SMEM>>>(p_xb, t_w1, b1, nullptr, nullptr,
                                        nullptr, nullptr, p_h, 256, 1024, 0, -1, 1);
    // 8. out = LN(x + h @ w2 + b2)
    gemm_ln<<<dim3(1, MY), 256, SMEMLN>>>(p_h, t_w2, b2, p_x, ln2g, ln2b, out, nullptr, 1024);
}

// round 14
// speedup vs baseline: 1.0442x; 1.0442x over previous
#include <cuda_runtime.h>
#include <cuda_bf16.h>
#include <cstdint>
#include <math.h>

// Problem constants (fixed by the dataset)
#define LEN    21760
#define BATCH  2
#define MTOK   (BATCH * LEN)          // 43520
#define DMODEL 256
#define DFFN   1024
#define NHEADS 8
#define LNEPS  1e-5f

typedef __nv_bfloat16 bf16;
typedef __nv_bfloat162 bf162;

// K-permutation within each 16-element group: [0,1,8,9,2,3,10,11,4,5,12,13,6,7,14,15]
// permk(k): element-level; pair-level (pi = k/2): nploc = ((pi&3)<<1)|((pi>>2)&1)
__host__ __device__ __forceinline__ int permk(int k) {
    return (k & ~15) | (((k >> 1) & 3) << 2) | (((k >> 3) & 1) << 1) | (k & 1);
}
__device__ __forceinline__ int permpair(int pi) {
    return (pi & ~7) | ((pi & 3) << 1) | ((pi >> 2) & 1);
}

// ---------------------------------------------------------------------------
// Scratch (device globals — no allocation).  All bf16 activation tensors are
// stored K-PERMUTED (within 16-col groups); fp32 tensors are unpermuted.
// ---------------------------------------------------------------------------
__device__ bf16  g_srcb [(size_t)MTOK * DMODEL];
__device__ bf16  g_qb   [(size_t)MTOK * DMODEL];
__device__ bf16  g_value[(size_t)MTOK * DMODEL];
__device__ float g_off  [(size_t)MTOK * DMODEL];
__device__ float g_attn [(size_t)MTOK * 128];
__device__ bf16  g_samp [(size_t)MTOK * DMODEL];
__device__ float g_x    [(size_t)MTOK * DMODEL];
__device__ bf16  g_xb   [(size_t)MTOK * DMODEL];
__device__ bf16  g_h    [(size_t)MTOK * DFFN];
// transposed bf16 weights [N, K] (K-major, K permuted)
__device__ bf16 g_wtval   [256 * 256];
__device__ bf16 g_wtoffat [384 * 256];    // rows 0-255: w_off; 256-383: w_attn
__device__ bf16 g_wtout   [256 * 256];
__device__ bf16 g_wt1     [1024 * 256];
__device__ bf16 g_wt2     [256 * 1024];

// ---------------------------------------------------------------------------
// Helpers
// ---------------------------------------------------------------------------
__device__ __forceinline__ uint32_t smem_u32(const void* p) {
    uint32_t a;
    asm("{ .reg .u64 t; cvta.to.shared.u64 t, %1; cvt.u32.u64 %0, t; }" : "=r"(a) : "l"(p));
    return a;
}
__device__ __forceinline__ void cp_async16(uint32_t saddr, const void* gaddr) {
    asm volatile("cp.async.cg.shared.global [%0], [%1], 16;" :: "r"(saddr), "l"(gaddr));
}
__device__ __forceinline__ void cp_commit() { asm volatile("cp.async.commit_group;"); }

__device__ __forceinline__ void mma_bf16(float* d, const uint32_t* a, const uint32_t* b) {
    asm volatile(
        "mma.sync.aligned.m16n8k16.row.col.f32.bf16.bf16.f32 "
        "{%0,%1,%2,%3}, {%4,%5,%6,%7}, {%8,%9}, {%0,%1,%2,%3};"
        : "+f"(d[0]), "+f"(d[1]), "+f"(d[2]), "+f"(d[3])
        : "r"(a[0]), "r"(a[1]), "r"(a[2]), "r"(a[3]), "r"(b[0]), "r"(b[1]));
}

// ---------------------------------------------------------------------------
// prep: srcb = bf16(src), qb = bf16(src + pos)   (written K-permuted)
// ---------------------------------------------------------------------------
__global__ __launch_bounds__(256)
void prep_kernel(const float* __restrict__ src, const float* __restrict__ pos,
                 bf16* __restrict__ srcb, bf16* __restrict__ qb, int n4)
{
    const int i = blockIdx.x * blockDim.x + threadIdx.x;
    if (i >= n4) return;
    float4 s = ((const float4*)src)[i];
    float4 p = ((const float4*)pos)[i];
    const int pi0 = permpair(2 * i);
    const int pi1 = permpair(2 * i + 1);
    ((bf162*)srcb)[pi0] = __floats2bfloat162_rn(s.x, s.y);
    ((bf162*)srcb)[pi1] = __floats2bfloat162_rn(s.z, s.w);
    ((bf162*)qb)[pi0] = __floats2bfloat162_rn(s.x + p.x, s.y + p.y);
    ((bf162*)qb)[pi1] = __floats2bfloat162_rn(s.z + p.z, s.w + p.w);
}

// ---------------------------------------------------------------------------
// All weight transposes in ONE launch. out[(rowOff+n)*K + permk(k)] = bf16(in[k*N+n])
// ---------------------------------------------------------------------------
struct TSeg { const float* in; bf16* out; int K, N, start, rowOff; };

__global__ void transpose_all(TSeg s0, TSeg s1, TSeg s2, TSeg s3, TSeg s4, TSeg s5)
{
    TSeg s;
    const int b = blockIdx.x;
    if      (b < s1.start) s = s0;
    else if (b < s2.start) s = s1;
    else if (b < s3.start) s = s2;
    else if (b < s4.start) s = s3;
    else if (b < s5.start) s = s4;
    else                   s = s5;

    const int local = b - s.start;
    const int tx_n  = s.N / 32;
    const int n0 = (local % tx_n) * 32;
    const int k0 = (local / tx_n) * 32;

    __shared__ float t[32][33];
    const int tx = threadIdx.x, ty = threadIdx.y;
#pragma unroll
    for (int j = 0; j < 32; j += 8)
        t[ty + j][tx] = s.in[(size_t)(k0 + ty + j) * s.N + n0 + tx];
    __syncthreads();
#pragma unroll
    for (int j = 0; j < 32; j += 8)
        s.out[(size_t)(s.rowOff + n0 + ty + j) * s.K + permk(k0 + tx)] = __float2bfloat16(t[tx][ty + j]);
}

// ---------------------------------------------------------------------------
// bf16 mma GEMM.  BM=BN=128, BK=64.  128 threads, 4 warps (2x2), warp 64x64.
// K-permuted layout: each thread's fragment quad is contiguous -> LDS.64.
// LDT=80 -> conflict-free LDS.64 (16-lane phases hit banks 8*gr+2*gc).
// ---------------------------------------------------------------------------
#define LDT 80
#define TBYTES (128 * LDT * 2)

__global__ __launch_bounds__(128, 2)
void gemm_bf(const bf16* __restrict__ A, const bf16* __restrict__ BT,
             const float* __restrict__ bias, const float* __restrict__ bias2,
             const unsigned char* __restrict__ mask,
             float* __restrict__ Cf, float* __restrict__ Cf2, bf16* __restrict__ Cb,
             int K, int N, int N2, int splitCol, int relu)
{
    extern __shared__ bf16 sm[];
    bf16* As = sm;
    bf16* Bs = sm + 2 * 128 * LDT;

    const int tid  = threadIdx.x;
    const int wid  = tid >> 5;
    const int lane = tid & 31;
    const int gr   = lane >> 2;
    const int gc   = lane & 3;
    const int wm   = wid & 1;          // row half (64)
    const int wn   = wid >> 1;         // col half (64)
    const int row0 = blockIdx.y * 128;
    const int col0 = blockIdx.x * 128;

    float acc[4][8][4];
#pragma unroll
    for (int mt = 0; mt < 4; mt++)
#pragma unroll
        for (int nt = 0; nt < 8; nt++)
#pragma unroll
            for (int r = 0; r < 4; r++) acc[mt][nt][r] = 0.f;

    const uint32_t sA = smem_u32(As);
    const uint32_t sB = smem_u32(Bs);

    const int nch = K >> 6;
    const int lrow = tid >> 3;          // 0..15
    const int lc   = (tid & 7) << 3;

    const bf16* Ab = A  + (size_t)(row0 + lrow) * K + lc;
    const bf16* Bb = BT + (size_t)(col0 + lrow) * K + lc;

#define LOAD_CHUNK(i) do {                                                        \
        const int _k0 = (i) << 6;                                                 \
        const uint32_t _abase = sA + ((i) & 1) * TBYTES;                          \
        const uint32_t _bbase = sB + ((i) & 1) * TBYTES;                          \
        _Pragma("unroll")                                                         \
        for (int it = 0; it < 8; it++) {                                          \
            const int r = it * 16;                                                \
            cp_async16(_abase + (uint32_t)(((lrow + r) * LDT + lc) * 2),          \
                       Ab + (size_t)r * K + _k0);                                 \
            cp_async16(_bbase + (uint32_t)(((lrow + r) * LDT + lc) * 2),          \
                       Bb + (size_t)r * K + _k0);                                 \
        }                                                                         \
        cp_commit();                                                              \
    } while (0)

    LOAD_CHUNK(0);

    for (int i = 0; i < nch; i++) {
        if (i + 1 < nch) {
            LOAD_CHUNK(i + 1);
            asm volatile("cp.async.wait_group 1;" ::: "memory");
        } else {
            asm volatile("cp.async.wait_group 0;" ::: "memory");
        }
        __syncthreads();

        const bf16* Ac = As + (i & 1) * (128 * LDT);
        const bf16* Bc = Bs + (i & 1) * (128 * LDT);

#pragma unroll
        for (int ks = 0; ks < 4; ks++) {
            const int kk = ks * 16;
            uint32_t af[4][4];
#pragma unroll
            for (int mt = 0; mt < 4; mt++) {
                const int r = wm * 64 + mt * 16 + gr;
                const uint2 a0 = *(const uint2*)&Ac[(r)     * LDT + kk + 4 * gc];
                const uint2 a1 = *(const uint2*)&Ac[(r + 8) * LDT + kk + 4 * gc];
                af[mt][0] = a0.x; af[mt][1] = a1.x; af[mt][2] = a0.y; af[mt][3] = a1.y;
            }
            uint32_t bfr[8][2];
#pragma unroll
            for (int nt = 0; nt < 8; nt++) {
                const int r = wn * 64 + nt * 8 + gr;
                const uint2 b0 = *(const uint2*)&Bc[r * LDT + kk + 4 * gc];
                bfr[nt][0] = b0.x; bfr[nt][1] = b0.y;
            }
#pragma unroll
            for (int mt = 0; mt < 4; mt++)
#pragma unroll
                for (int nt = 0; nt < 8; nt++)
                    mma_bf16(acc[mt][nt], af[mt], bfr[nt]);
        }
        __syncthreads();
    }

    const bool second = (splitCol >= 0) && (col0 >= splitCol);
    const float* biasP = second ? bias2 : bias;
    float* CfP = second ? Cf2 : Cf;
    const int  Nout  = second ? N2 : N;
    const int  cbase = second ? col0 - splitCol : col0;

#pragma unroll
    for (int mt = 0; mt < 4; mt++) {
        const int r0 = row0 + wm * 64 + mt * 16 + gr;
        const bool m0 = mask && mask[r0];
        const bool m1 = mask && mask[r0 + 8];
#pragma unroll
        for (int nt = 0; nt < 8; nt++) {
            const int col = cbase + wn * 64 + nt * 8 + gc * 2;
            const float b0 = __ldg(biasP + col);
            const float b1 = __ldg(biasP + col + 1);
            float v0 = acc[mt][nt][0] + b0, v1 = acc[mt][nt][1] + b1;
            float v2 = acc[mt][nt][2] + b0, v3 = acc[mt][nt][3] + b1;
            if (relu) {
                v0 = fmaxf(v0, 0.f); v1 = fmaxf(v1, 0.f);
                v2 = fmaxf(v2, 0.f); v3 = fmaxf(v3, 0.f);
            }
            if (m0) { v0 = v1 = 0.f; }
            if (m1) { v2 = v3 = 0.f; }
            if (CfP) {
                *(float2*)(CfP + (size_t)r0 * Nout + col)       = make_float2(v0, v1);
                *(float2*)(CfP + (size_t)(r0 + 8) * Nout + col) = make_float2(v2, v3);
            }
            if (Cb) {
                // bf16 outputs feed downstream GEMM A operands -> store K-permuted
                const int npi2 = permpair(col >> 1) * 2;
                *(bf162*)(Cb + (size_t)r0 * Nout + npi2)       = __floats2bfloat162_rn(v0, v1);
                *(bf162*)(Cb + (size_t)(r0 + 8) * Nout + npi2) = __floats2bfloat162_rn(v2, v3);
            }
        }
    }
}

// ---------------------------------------------------------------------------
// GEMM + bias + residual + LayerNorm fused.  N = 256 (full row per CTA).
// BM=128, BN=256, 256 threads (8 warps 2x4), warp tile 64x64.  Permuted
// fragment loads (LDS.64), same as gemm_bf.
// ---------------------------------------------------------------------------
__global__ __launch_bounds__(256, 1)
void gemm_ln(const bf16* __restrict__ A, const bf16* __restrict__ BT,
             const float* __restrict__ bias, const float* __restrict__ res,
             const float* __restrict__ lng, const float* __restrict__ lnb,
             float* __restrict__ Of, bf16* __restrict__ Ob, int K)
{
    extern __shared__ bf16 sm[];
    bf16* As = sm;                       // [2][128][80]
    bf16* Bs = sm + 2 * 128 * LDT;       // [2][256][80]

    const int tid  = threadIdx.x;
    const int wid  = tid >> 5;
    const int lane = tid & 31;
    const int gr   = lane >> 2;
    const int gc   = lane & 3;
    const int wm   = wid & 1;            // row half (64)
    const int wn   = wid >> 1;           // col quarter (64)
    const int row0 = blockIdx.y * 128;

    const uint32_t sA = smem_u32(As);
    const uint32_t sB = smem_u32(Bs);

    float acc[4][8][4];
#pragma unroll
    for (int mt = 0; mt < 4; mt++)
#pragma unroll
        for (int nt = 0; nt < 8; nt++)
#pragma unroll
            for (int r = 0; r < 4; r++) acc[mt][nt][r] = 0.f;

    const int nch = K >> 6;
    const int lrow = tid >> 3;           // 0..31
    const int lc   = (tid & 7) << 3;

#define LN_LOAD(i) do {                                                            \
        const int _k0 = (i) << 6;                                                  \
        const uint32_t _ab = sA + ((i) & 1) * TBYTES;                              \
        const uint32_t _bb = sB + ((i) & 1) * (256 * LDT * 2);                     \
        _Pragma("unroll")                                                          \
        for (int it = 0; it < 4; it++) {                                           \
            const int r = lrow + it * 32;                                          \
            cp_async16(_ab + (uint32_t)((r * LDT + lc) * 2),                       \
                       A + (size_t)(row0 + r) * K + lc + _k0);                     \
        }                                                                          \
        _Pragma("unroll")                                                          \
        for (int it = 0; it < 8; it++) {                                           \
            const int r = lrow + it * 32;                                          \
            cp_async16(_bb + (uint32_t)((r * LDT + lc) * 2),                       \
                       BT + (size_t)r * K + lc + _k0);                             \
        }                                                                          \
        cp_commit();                                                               \
    } while (0)

    LN_LOAD(0);

    for (int i = 0; i < nch; i++) {
        if (i + 1 < nch) {
            LN_LOAD(i + 1);
            asm volatile("cp.async.wait_group 1;" ::: "memory");
        } else {
            asm volatile("cp.async.wait_group 0;" ::: "memory");
        }
        __syncthreads();

        const bf16* Ac = As + (i & 1) * (128 * LDT);
        const bf16* Bc = Bs + (i & 1) * (256 * LDT);

#pragma unroll
        for (int ks = 0; ks < 4; ks++) {
            const int kk = ks * 16;
            uint32_t af[4][4];
#pragma unroll
            for (int mt = 0; mt < 4; mt++) {
                const int r = wm * 64 + mt * 16 + gr;
                const uint2 a0 = *(const uint2*)&Ac[(r)     * LDT + kk + 4 * gc];
                const uint2 a1 = *(const uint2*)&Ac[(r + 8) * LDT + kk + 4 * gc];
                af[mt][0] = a0.x; af[mt][1] = a1.x; af[mt][2] = a0.y; af[mt][3] = a1.y;
            }
            uint32_t bfr[8][2];
#pragma unroll
            for (int nt = 0; nt < 8; nt++) {
                const int r = wn * 64 + nt * 8 + gr;
                const uint2 b0 = *(const uint2*)&Bc[r * LDT + kk + 4 * gc];
                bfr[nt][0] = b0.x; bfr[nt][1] = b0.y;
            }
#pragma unroll
            for (int mt = 0; mt < 4; mt++)
#pragma unroll
                for (int nt = 0; nt < 8; nt++)
                    mma_bf16(acc[mt][nt], af[mt], bfr[nt]);
        }
        __syncthreads();
    }

    // ---- fused bias + residual + LayerNorm ----
    float2* sred = (float2*)sm;          // [128][4] partials

#pragma unroll
    for (int mt = 0; mt < 4; mt++) {
        const int rA = wm * 64 + mt * 16 + gr;
        const int rB = rA + 8;
        float sA2 = 0.f, qA = 0.f, sB2 = 0.f, qB = 0.f;
#pragma unroll
        for (int nt = 0; nt < 8; nt++) {
            const int col = wn * 64 + nt * 8 + gc * 2;
            const float b0 = __ldg(bias + col);
            const float b1 = __ldg(bias + col + 1);
            const float2 rs0 = *(const float2*)(res + (size_t)(row0 + rA) * 256 + col);
            const float2 rs1 = *(const float2*)(res + (size_t)(row0 + rB) * 256 + col);
            acc[mt][nt][0] += b0 + rs0.x;
            acc[mt][nt][1] += b1 + rs0.y;
            acc[mt][nt][2] += b0 + rs1.x;
            acc[mt][nt][3] += b1 + rs1.y;
            sA2 += acc[mt][nt][0] + acc[mt][nt][1];
            qA  += acc[mt][nt][0] * acc[mt][nt][0] + acc[mt][nt][1] * acc[mt][nt][1];
            sB2 += acc[mt][nt][2] + acc[mt][nt][3];
            qB  += acc[mt][nt][2] * acc[mt][nt][2] + acc[mt][nt][3] * acc[mt][nt][3];
        }
#pragma unroll
        for (int o = 1; o <= 2; o <<= 1) {
            sA2 += __shfl_xor_sync(0xffffffffu, sA2, o);
            qA  += __shfl_xor_sync(0xffffffffu, qA,  o);
            sB2 += __shfl_xor_sync(0xffffffffu, sB2, o);
            qB  += __shfl_xor_sync(0xffffffffu, qB,  o);
        }
        if (gc == 0) {
            sred[rA * 4 + wn] = make_float2(sA2, qA);
            sred[rB * 4 + wn] = make_float2(sB2, qB);
        }
    }
    __syncthreads();

#pragma unroll
    for (int mt = 0; mt < 4; mt++) {
        const int rA = wm * 64 + mt * 16 + gr;
        const int rB = rA + 8;
        float2 pA = make_float2(0.f, 0.f), pB = make_float2(0.f, 0.f);
#pragma unroll
        for (int w = 0; w < 4; w++) {
            float2 a = sred[rA * 4 + w]; pA.x += a.x; pA.y += a.y;
            float2 b = sred[rB * 4 + w]; pB.x += b.x; pB.y += b.y;
        }
        const float mA = pA.x * (1.f / 256.f);
        const float vA = fmaxf(pA.y * (1.f / 256.f) - mA * mA, 0.f);
        const float rAst = rsqrtf(vA + LNEPS);
        const float mB = pB.x * (1.f / 256.f);
        const float vB = fmaxf(pB.y * (1.f / 256.f) - mB * mB, 0.f);
        const float rBst = rsqrtf(vB + LNEPS);

#pragma unroll
        for (int nt = 0; nt < 8; nt++) {
            const int col = wn * 64 + nt * 8 + gc * 2;
            const float g0 = __ldg(lng + col),  g1 = __ldg(lng + col + 1);
            const float e0 = __ldg(lnb + col),  e1 = __ldg(lnb + col + 1);
            const float o0 = (acc[mt][nt][0] - mA) * rAst * g0 + e0;
            const float o1 = (acc[mt][nt][1] - mA) * rAst * g1 + e1;
            const float o2 = (acc[mt][nt][2] - mB) * rBst * g0 + e0;
            const float o3 = (acc[mt][nt][3] - mB) * rBst * g1 + e1;
            *(float2*)(Of + (size_t)(row0 + rA) * 256 + col) = make_float2(o0, o1);
            *(float2*)(Of + (size_t)(row0 + rB) * 256 + col) = make_float2(o2, o3);
            if (Ob) {
                const int npi2 = permpair(col >> 1) * 2;
                *(bf162*)(Ob + (size_t)(row0 + rA) * 256 + npi2) = __floats2bfloat162_rn(o0, o1);
                *(bf162*)(Ob + (size_t)(row0 + rB) * 256 + npi2) = __floats2bfloat162_rn(o2, o3);
            }
        }
    }
}

// ---------------------------------------------------------------------------
// Deformable-attention sampling.  One warp per (token, head).
// Operates entirely in the K-permuted channel space (bilinear weights are
// channel-uniform, so no unpermute needed): reads permuted value, writes
// permuted samp at the same stored positions.
// ---------------------------------------------------------------------------
__global__ __launch_bounds__(256)
void samp_kernel(const bf16* __restrict__ value, const float* __restrict__ attn,
                 const float* __restrict__ off,  const float* __restrict__ ref,
                 bf16* __restrict__ out)
{
    const int gw   = (blockIdx.x * blockDim.x + threadIdx.x) >> 5;
    const int lane = threadIdx.x & 31;
    if (gw >= MTOK * NHEADS) return;

    const int h    = gw & 7;
    const int bl   = gw >> 3;
    const int b    = (bl >= LEN) ? 1 : 0;
    const int pgrp = lane >> 3;          // point within level
    const int cq   = lane & 7;           // channel quad

    // softmax across lanes (lanes 0..15 hold the 16 logits)
    float logit = (lane < 16) ? __ldg(attn + bl * 128 + h * 16 + lane) : -1e30f;
    float m = logit;
#pragma unroll
    for (int o = 16; o > 0; o >>= 1) m = fmaxf(m, __shfl_xor_sync(0xffffffffu, m, o));
    float e = (lane < 16) ? __expf(logit - m) : 0.f;
    float s = e;
#pragma unroll
    for (int o = 16; o > 0; o >>= 1) s += __shfl_xor_sync(0xffffffffu, s, o);
    const float wn = e / s;

    const float ov = __ldg(off + bl * 256 + h * 32 + lane);   // 32 offsets
    const float rv = (lane < 8) ? __ldg(ref + bl * 8 + lane) : 0.f;

    const int Hs[4] = {128, 64, 32, 16};
    const int Ss[4] = {0, 16384, 20480, 21504};

    float4 acc4 = make_float4(0.f, 0.f, 0.f, 0.f);
#pragma unroll
    for (int l = 0; l < 4; l++) {
        const int   Wl = Hs[l];
        const float fW = (float)Wl;
        const float rx = __shfl_sync(0xffffffffu, rv, 2 * l);
        const float ry = __shfl_sync(0xffffffffu, rv, 2 * l + 1);
        const uint2* vb = (const uint2*)(value + (size_t)(b * LEN + Ss[l]) * 256 + h * 32) + cq;

        const float ox = __shfl_sync(0xffffffffu, ov, l * 8 + pgrp * 2);
        const float oy = __shfl_sync(0xffffffffu, ov, l * 8 + pgrp * 2 + 1);
        const float aw = __shfl_sync(0xffffffffu, wn, l * 4 + pgrp);
        const float x  = fmaf(rx, fW, ox) - 0.5f;
        const float y  = fmaf(ry, fW, oy) - 0.5f;
        const float x0f = floorf(x), y0f = floorf(y);
        const float dx = x - x0f, dy = y - y0f;
        const int   x0 = (int)x0f, y0 = (int)y0f;

        float4 psum = make_float4(0.f, 0.f, 0.f, 0.f);
#pragma unroll
        for (int c = 0; c < 4; c++) {
            const int xi = x0 + (c & 1);
            const int yi = y0 + (c >> 1);
            const float cw = ((c & 1) ? dx : 1.f - dx) * ((c >> 1) ? dy : 1.f - dy);
            const bool valid = (xi >= 0) & (xi < Wl) & (yi >= 0) & (yi < Wl);
            const int xc = min(max(xi, 0), Wl - 1);
            const int yc = min(max(yi, 0), Wl - 1);
            const uint2 raw = vb[(size_t)(yc * Wl + xc) * 64];   // 64 uint2 per 256-bf16 token row
            const float2 v0 = __bfloat1622float2(*(const bf162*)&raw.x);
            const float2 v1 = __bfloat1622float2(*(const bf162*)&raw.y);
            const float w = valid ? cw : 0.f;
            psum.x = fmaf(v0.x, w, psum.x);
            psum.y = fmaf(v0.y, w, psum.y);
            psum.z = fmaf(v1.x, w, psum.z);
            psum.w = fmaf(v1.y, w, psum.w);
        }
        acc4.x = fmaf(aw, psum.x, acc4.x);
        acc4.y = fmaf(aw, psum.y, acc4.y);
        acc4.z = fmaf(aw, psum.z, acc4.z);
        acc4.w = fmaf(aw, psum.w, acc4.w);
    }
    // reduce across the 4 point-groups (lane bits 3,4)
#pragma unroll
    for (int o = 8; o <= 16; o <<= 1) {
        acc4.x += __shfl_xor_sync(0xffffffffu, acc4.x, o);
        acc4.y += __shfl_xor_sync(0xffffffffu, acc4.y, o);
        acc4.z += __shfl_xor_sync(0xffffffffu, acc4.z, o);
        acc4.w += __shfl_xor_sync(0xffffffffu, acc4.w, o);
    }
    if (pgrp == 0) {
        uint2 packed;
        bf162 p0 = __floats2bfloat162_rn(acc4.x, acc4.y);
        bf162 p1 = __floats2bfloat162_rn(acc4.z, acc4.w);
        packed.x = *(const uint32_t*)&p0;
        packed.y = *(const uint32_t*)&p1;
        ((uint2*)(out + (size_t)bl * 256 + h * 32))[cq] = packed;
    }
}

// ---------------------------------------------------------------------------
// Launch
// ---------------------------------------------------------------------------
extern "C" void kernel_launch(void* const* d_in, const int* in_sizes, int n_in,
                              void* d_out, int out_size)
{
    const float* src  = (const float*)d_in[0];
    const float* pos  = (const float*)d_in[1];
    const float* ref  = (const float*)d_in[2];
    const unsigned char* mask = (const unsigned char*)d_in[5];
    const float* w_off  = (const float*)d_in[6];
    const float* b_off  = (const float*)d_in[7];
    const float* w_attn = (const float*)d_in[8];
    const float* b_attn = (const float*)d_in[9];
    const float* w_val  = (const float*)d_in[10];
    const float* b_val  = (const float*)d_in[11];
    const float* w_out  = (const float*)d_in[12];
    const float* b_out  = (const float*)d_in[13];
    const float* ln1g   = (const float*)d_in[14];
    const float* ln1b   = (const float*)d_in[15];
    const float* w1     = (const float*)d_in[16];
    const float* b1     = (const float*)d_in[17];
    const float* w2     = (const float*)d_in[18];
    const float* b2     = (const float*)d_in[19];
    const float* ln2g   = (const float*)d_in[20];
    const float* ln2b   = (const float*)d_in[21];
    float* out = (float*)d_out;

    bf16 *p_srcb, *p_qb, *p_value, *p_samp, *p_xb, *p_h;
    float *p_off, *p_attn, *p_x;
    bf16 *t_val, *t_offat, *t_out, *t_w1, *t_w2;
    cudaGetSymbolAddress((void**)&p_srcb,  g_srcb);
    cudaGetSymbolAddress((void**)&p_qb,    g_qb);
    cudaGetSymbolAddress((void**)&p_value, g_value);
    cudaGetSymbolAddress((void**)&p_off,   g_off);
    cudaGetSymbolAddress((void**)&p_attn,  g_attn);
    cudaGetSymbolAddress((void**)&p_samp,  g_samp);
    cudaGetSymbolAddress((void**)&p_x,     g_x);
    cudaGetSymbolAddress((void**)&p_xb,    g_xb);
    cudaGetSymbolAddress((void**)&p_h,     g_h);
    cudaGetSymbolAddress((void**)&t_val,   g_wtval);
    cudaGetSymbolAddress((void**)&t_offat, g_wtoffat);
    cudaGetSymbolAddress((void**)&t_out,   g_wtout);
    cudaGetSymbolAddress((void**)&t_w1,    g_wt1);
    cudaGetSymbolAddress((void**)&t_w2,    g_wt2);

    const int SMEM   = 2 * 2 * 128 * LDT * 2;                       // 81920
    const int SMEMLN = 2 * (128 + 256) * LDT * 2;                   // 122880
    cudaFuncSetAttribute(gemm_bf, cudaFuncAttributeMaxDynamicSharedMemorySize, SMEM);
    cudaFuncSetAttribute(gemm_ln, cudaFuncAttributeMaxDynamicSharedMemorySize, SMEMLN);

    const int MY = MTOK / 128;   // 340

    // 1. srcb = bf16(src); qb = bf16(src + pos)   (K-permuted)
    prep_kernel<<<(MTOK * 256 / 4 + 255) / 256, 256>>>(src, pos, p_srcb, p_qb, MTOK * 256 / 4);

    // 2. all weight transposes in one launch (K-permuted)
    TSeg s0 = { w_val,  t_val,   256, 256,   0,   0 };
    TSeg s1 = { w_off,  t_offat, 256, 256,  64,   0 };
    TSeg s2 = { w_attn, t_offat, 256, 128, 128, 256 };
    TSeg s3 = { w_out,  t_out,   256, 256, 160,   0 };
    TSeg s4 = { w1,     t_w1,    256, 1024, 224,  0 };
    TSeg s5 = { w2,     t_w2,    1024, 256, 480,  0 };
    transpose_all<<<736, dim3(32, 8)>>>(s0, s1, s2, s3, s4, s5);

    // 3. value = srcb @ w_val + b_val (masked), bf16 out (permuted)
    gemm_bf<<<dim3(2, MY), 128, SMEM>>>(p_srcb, t_val, b_val, nullptr, mask,
                                        nullptr, nullptr, p_value, 256, 256, 0, -1, 0);
    // 4. [off | attn] = qb @ t_offat  (split epilogue, fp32 unpermuted)
    gemm_bf<<<dim3(3, MY), 128, SMEM>>>(p_qb, t_offat, b_off, b_attn, nullptr,
                                        p_off, p_attn, nullptr, 256, 256, 128, 256, 0);
    // 5. deformable sampling (permuted in/out)
    samp_kernel<<<(MTOK * NHEADS) / 8, 256>>>(p_value, p_attn, p_off, ref, p_samp);
    // 6. x = LN(src + samp @ w_out + b_out)  -> fp32 (unperm) + bf16 (perm)
    gemm_ln<<<dim3(1, MY), 256, SMEMLN>>>(p_samp, t_out, b_out, src, ln1g, ln1b, p_x, p_xb, 256);
    // 7. h = relu(xb @ w1 + b1), bf16 out (permuted)
    gemm_bf<<<dim3(8, MY), 128, SMEM>>>(p_xb, t_w1, b1, nullptr, nullptr,
                                        nullptr, nullptr, p_h, 256, 1024, 0, -1, 1);
    // 8. out = LN(x + h @ w2 + b2)  (fp32 unpermuted)
    gemm_ln<<<dim3(1, MY), 256, SMEMLN>>>(p_h, t_w2, b2, p_x, ln2g, ln2b, out, nullptr, 1024);
}

// round 15
// speedup vs baseline: 1.0513x; 1.0069x over previous
#include <cuda_runtime.h>
#include <cuda_bf16.h>
#include <cstdint>
#include <math.h>

// Problem constants (fixed by the dataset)
#define LEN    21760
#define BATCH  2
#define MTOK   (BATCH * LEN)          // 43520
#define DMODEL 256
#define DFFN   1024
#define NHEADS 8
#define LNEPS  1e-5f

typedef __nv_bfloat16 bf16;
typedef __nv_bfloat162 bf162;

// K-permutation within each 16-element group: [0,1,8,9,2,3,10,11,4,5,12,13,6,7,14,15]
__host__ __device__ __forceinline__ int permk(int k) {
    return (k & ~15) | (((k >> 1) & 3) << 2) | (((k >> 3) & 1) << 1) | (k & 1);
}
__device__ __forceinline__ int permpair(int pi) {
    return (pi & ~7) | ((pi & 3) << 1) | ((pi >> 2) & 1);
}

// ---------------------------------------------------------------------------
// Scratch (device globals — no allocation).  bf16 activations K-permuted.
// ---------------------------------------------------------------------------
__device__ bf16  g_srcb [(size_t)MTOK * DMODEL];
__device__ bf16  g_qb   [(size_t)MTOK * DMODEL];
__device__ bf16  g_value[(size_t)MTOK * DMODEL];
__device__ float g_off  [(size_t)MTOK * DMODEL];
__device__ float g_attn [(size_t)MTOK * 128];
__device__ bf16  g_samp [(size_t)MTOK * DMODEL];
__device__ float g_x    [(size_t)MTOK * DMODEL];
__device__ bf16  g_xb   [(size_t)MTOK * DMODEL];
__device__ bf16  g_h    [(size_t)MTOK * DFFN];
// transposed bf16 weights [N, K] (K-major, K permuted)
__device__ bf16 g_wtval   [256 * 256];
__device__ bf16 g_wtoffat [384 * 256];
__device__ bf16 g_wtout   [256 * 256];
__device__ bf16 g_wt1     [1024 * 256];
__device__ bf16 g_wt2     [256 * 1024];

// ---------------------------------------------------------------------------
// Helpers
// ---------------------------------------------------------------------------
__device__ __forceinline__ uint32_t smem_u32(const void* p) {
    uint32_t a;
    asm("{ .reg .u64 t; cvta.to.shared.u64 t, %1; cvt.u32.u64 %0, t; }" : "=r"(a) : "l"(p));
    return a;
}
__device__ __forceinline__ void cp_async16(uint32_t saddr, const void* gaddr) {
    asm volatile("cp.async.cg.shared.global [%0], [%1], 16;" :: "r"(saddr), "l"(gaddr));
}
__device__ __forceinline__ void cp_commit() { asm volatile("cp.async.commit_group;"); }

__device__ __forceinline__ void mma_bf16(float* d, const uint32_t* a, const uint32_t* b) {
    asm volatile(
        "mma.sync.aligned.m16n8k16.row.col.f32.bf16.bf16.f32 "
        "{%0,%1,%2,%3}, {%4,%5,%6,%7}, {%8,%9}, {%0,%1,%2,%3};"
        : "+f"(d[0]), "+f"(d[1]), "+f"(d[2]), "+f"(d[3])
        : "r"(a[0]), "r"(a[1]), "r"(a[2]), "r"(a[3]), "r"(b[0]), "r"(b[1]));
}

// Swizzled smem addressing: rows of 128B (64 bf16), 16B chunks, chunk XOR (row&3)<<1.
// Store (loader): row, chunk c (0..7)
__device__ __forceinline__ uint32_t swz_store(int row, int c) {
    return (uint32_t)(row * 128 + ((c ^ ((row & 3) << 1)) << 4));
}
// Fragment LDS.64: row r, K-substep base kk (elements), gc = lane&3
__device__ __forceinline__ uint32_t swz_frag(int r, int kk, int gc) {
    const int chunk = (kk >> 3) + (gc >> 1);
    return (uint32_t)(r * 128 + ((chunk ^ ((r & 3) << 1)) << 4) + ((gc & 1) << 3));
}

// ---------------------------------------------------------------------------
// prep: srcb = bf16(src), qb = bf16(src + pos)   (K-permuted)
// ---------------------------------------------------------------------------
__global__ __launch_bounds__(256)
void prep_kernel(const float* __restrict__ src, const float* __restrict__ pos,
                 bf16* __restrict__ srcb, bf16* __restrict__ qb, int n4)
{
    const int i = blockIdx.x * blockDim.x + threadIdx.x;
    if (i >= n4) return;
    float4 s = ((const float4*)src)[i];
    float4 p = ((const float4*)pos)[i];
    const int pi0 = permpair(2 * i);
    const int pi1 = permpair(2 * i + 1);
    ((bf162*)srcb)[pi0] = __floats2bfloat162_rn(s.x, s.y);
    ((bf162*)srcb)[pi1] = __floats2bfloat162_rn(s.z, s.w);
    ((bf162*)qb)[pi0] = __floats2bfloat162_rn(s.x + p.x, s.y + p.y);
    ((bf162*)qb)[pi1] = __floats2bfloat162_rn(s.z + p.z, s.w + p.w);
}

// ---------------------------------------------------------------------------
// All weight transposes in ONE launch. out[(rowOff+n)*K + permk(k)] = bf16(in[k*N+n])
// ---------------------------------------------------------------------------
struct TSeg { const float* in; bf16* out; int K, N, start, rowOff; };

__global__ void transpose_all(TSeg s0, TSeg s1, TSeg s2, TSeg s3, TSeg s4, TSeg s5)
{
    TSeg s;
    const int b = blockIdx.x;
    if      (b < s1.start) s = s0;
    else if (b < s2.start) s = s1;
    else if (b < s3.start) s = s2;
    else if (b < s4.start) s = s3;
    else if (b < s5.start) s = s4;
    else                   s = s5;

    const int local = b - s.start;
    const int tx_n  = s.N / 32;
    const int n0 = (local % tx_n) * 32;
    const int k0 = (local / tx_n) * 32;

    __shared__ float t[32][33];
    const int tx = threadIdx.x, ty = threadIdx.y;
#pragma unroll
    for (int j = 0; j < 32; j += 8)
        t[ty + j][tx] = s.in[(size_t)(k0 + ty + j) * s.N + n0 + tx];
    __syncthreads();
#pragma unroll
    for (int j = 0; j < 32; j += 8)
        s.out[(size_t)(s.rowOff + n0 + ty + j) * s.K + permk(k0 + tx)] = __float2bfloat16(t[tx][ty + j]);
}

// ---------------------------------------------------------------------------
// bf16 mma GEMM.  BM=BN=128, BK=64.  128 threads, 4 warps (2x2), warp 64x64.
// K-permuted layout + swizzled smem (no padding): LDS.64 fragments.
// Smem: 2 x (128+128) rows x 128B = 64 KB -> 3 CTAs/SM.
// ---------------------------------------------------------------------------
#define TROWB 128                     // bytes per smem row
#define TBYTES (128 * TROWB)          // one tile buffer (128 rows)

__global__ __launch_bounds__(128, 3)
void gemm_bf(const bf16* __restrict__ A, const bf16* __restrict__ BT,
             const float* __restrict__ bias, const float* __restrict__ bias2,
             const unsigned char* __restrict__ mask,
             float* __restrict__ Cf, float* __restrict__ Cf2, bf16* __restrict__ Cb,
             int K, int N, int N2, int splitCol, int relu)
{
    extern __shared__ bf16 sm[];
    const uint32_t sA = smem_u32(sm);
    const uint32_t sB = sA + 2 * TBYTES;

    const int tid  = threadIdx.x;
    const int wid  = tid >> 5;
    const int lane = tid & 31;
    const int gr   = lane >> 2;
    const int gc   = lane & 3;
    const int wm   = wid & 1;          // row half (64)
    const int wn   = wid >> 1;         // col half (64)
    const int row0 = blockIdx.y * 128;
    const int col0 = blockIdx.x * 128;

    float acc[4][8][4];
#pragma unroll
    for (int mt = 0; mt < 4; mt++)
#pragma unroll
        for (int nt = 0; nt < 8; nt++)
#pragma unroll
            for (int r = 0; r < 4; r++) acc[mt][nt][r] = 0.f;

    const int nch = K >> 6;
    const int lrow = tid >> 3;          // 0..15
    const int lchk = tid & 7;           // chunk 0..7
    const int lc   = lchk << 3;         // element offset

    const bf16* Ab = A  + (size_t)(row0 + lrow) * K + lc;
    const bf16* Bb = BT + (size_t)(col0 + lrow) * K + lc;

#define LOAD_CHUNK(i) do {                                                        \
        const int _k0 = (i) << 6;                                                 \
        const uint32_t _abase = sA + ((i) & 1) * TBYTES;                          \
        const uint32_t _bbase = sB + ((i) & 1) * TBYTES;                          \
        _Pragma("unroll")                                                         \
        for (int it = 0; it < 8; it++) {                                          \
            const int r = lrow + it * 16;                                         \
            cp_async16(_abase + swz_store(r, lchk), Ab + (size_t)(it * 16) * K + _k0); \
            cp_async16(_bbase + swz_store(r, lchk), Bb + (size_t)(it * 16) * K + _k0); \
        }                                                                         \
        cp_commit();                                                              \
    } while (0)

    LOAD_CHUNK(0);

    for (int i = 0; i < nch; i++) {
        if (i + 1 < nch) {
            LOAD_CHUNK(i + 1);
            asm volatile("cp.async.wait_group 1;" ::: "memory");
        } else {
            asm volatile("cp.async.wait_group 0;" ::: "memory");
        }
        __syncthreads();

        const uint32_t sAc = sA + (i & 1) * TBYTES;
        const uint32_t sBc = sB + (i & 1) * TBYTES;

#pragma unroll
        for (int ks = 0; ks < 4; ks++) {
            const int kk = ks * 16;
            uint32_t af[4][4];
#pragma unroll
            for (int mt = 0; mt < 4; mt++) {
                const int r = wm * 64 + mt * 16 + gr;
                uint2 a0, a1;
                asm volatile("ld.shared.v2.b32 {%0,%1}, [%2];" : "=r"(a0.x), "=r"(a0.y) : "r"(sAc + swz_frag(r, kk, gc)));
                asm volatile("ld.shared.v2.b32 {%0,%1}, [%2];" : "=r"(a1.x), "=r"(a1.y) : "r"(sAc + swz_frag(r + 8, kk, gc)));
                af[mt][0] = a0.x; af[mt][1] = a1.x; af[mt][2] = a0.y; af[mt][3] = a1.y;
            }
            uint32_t bfr[8][2];
#pragma unroll
            for (int nt = 0; nt < 8; nt++) {
                const int r = wn * 64 + nt * 8 + gr;
                uint2 b0;
                asm volatile("ld.shared.v2.b32 {%0,%1}, [%2];" : "=r"(b0.x), "=r"(b0.y) : "r"(sBc + swz_frag(r, kk, gc)));
                bfr[nt][0] = b0.x; bfr[nt][1] = b0.y;
            }
#pragma unroll
            for (int mt = 0; mt < 4; mt++)
#pragma unroll
                for (int nt = 0; nt < 8; nt++)
                    mma_bf16(acc[mt][nt], af[mt], bfr[nt]);
        }
        __syncthreads();
    }

    const bool second = (splitCol >= 0) && (col0 >= splitCol);
    const float* biasP = second ? bias2 : bias;
    float* CfP = second ? Cf2 : Cf;
    const int  Nout  = second ? N2 : N;
    const int  cbase = second ? col0 - splitCol : col0;

#pragma unroll
    for (int mt = 0; mt < 4; mt++) {
        const int r0 = row0 + wm * 64 + mt * 16 + gr;
        const bool m0 = mask && mask[r0];
        const bool m1 = mask && mask[r0 + 8];
#pragma unroll
        for (int nt = 0; nt < 8; nt++) {
            const int col = cbase + wn * 64 + nt * 8 + gc * 2;
            const float b0 = __ldg(biasP + col);
            const float b1 = __ldg(biasP + col + 1);
            float v0 = acc[mt][nt][0] + b0, v1 = acc[mt][nt][1] + b1;
            float v2 = acc[mt][nt][2] + b0, v3 = acc[mt][nt][3] + b1;
            if (relu) {
                v0 = fmaxf(v0, 0.f); v1 = fmaxf(v1, 0.f);
                v2 = fmaxf(v2, 0.f); v3 = fmaxf(v3, 0.f);
            }
            if (m0) { v0 = v1 = 0.f; }
            if (m1) { v2 = v3 = 0.f; }
            if (CfP) {
                *(float2*)(CfP + (size_t)r0 * Nout + col)       = make_float2(v0, v1);
                *(float2*)(CfP + (size_t)(r0 + 8) * Nout + col) = make_float2(v2, v3);
            }
            if (Cb) {
                const int npi2 = permpair(col >> 1) * 2;
                *(bf162*)(Cb + (size_t)r0 * Nout + npi2)       = __floats2bfloat162_rn(v0, v1);
                *(bf162*)(Cb + (size_t)(r0 + 8) * Nout + npi2) = __floats2bfloat162_rn(v2, v3);
            }
        }
    }
}

// ---------------------------------------------------------------------------
// GEMM + bias + residual + LayerNorm fused.  N = 256 (full row per CTA).
// BM=128, BN=256, 256 threads (8 warps 2x4), warp tile 64x64, swizzled smem.
// ---------------------------------------------------------------------------
__global__ __launch_bounds__(256, 1)
void gemm_ln(const bf16* __restrict__ A, const bf16* __restrict__ BT,
             const float* __restrict__ bias, const float* __restrict__ res,
             const float* __restrict__ lng, const float* __restrict__ lnb,
             float* __restrict__ Of, bf16* __restrict__ Ob, int K)
{
    extern __shared__ bf16 sm[];
    const uint32_t sA = smem_u32(sm);                 // 2 x 128 rows
    const uint32_t sB = sA + 2 * TBYTES;              // 2 x 256 rows

    const int tid  = threadIdx.x;
    const int wid  = tid >> 5;
    const int lane = tid & 31;
    const int gr   = lane >> 2;
    const int gc   = lane & 3;
    const int wm   = wid & 1;            // row half (64)
    const int wn   = wid >> 1;           // col quarter (64)
    const int row0 = blockIdx.y * 128;

    float acc[4][8][4];
#pragma unroll
    for (int mt = 0; mt < 4; mt++)
#pragma unroll
        for (int nt = 0; nt < 8; nt++)
#pragma unroll
            for (int r = 0; r < 4; r++) acc[mt][nt][r] = 0.f;

    const int nch = K >> 6;
    const int lrow = tid >> 3;           // 0..31
    const int lchk = tid & 7;
    const int lc   = lchk << 3;

#define LN_LOAD(i) do {                                                            \
        const int _k0 = (i) << 6;                                                  \
        const uint32_t _ab = sA + ((i) & 1) * TBYTES;                              \
        const uint32_t _bb = sB + ((i) & 1) * (256 * TROWB);                       \
        _Pragma("unroll")                                                          \
        for (int it = 0; it < 4; it++) {                                           \
            const int r = lrow + it * 32;                                          \
            cp_async16(_ab + swz_store(r, lchk),                                   \
                       A + (size_t)(row0 + r) * K + lc + _k0);                     \
        }                                                                          \
        _Pragma("unroll")                                                          \
        for (int it = 0; it < 8; it++) {                                           \
            const int r = lrow + it * 32;                                          \
            cp_async16(_bb + swz_store(r, lchk),                                   \
                       BT + (size_t)r * K + lc + _k0);                             \
        }                                                                          \
        cp_commit();                                                               \
    } while (0)

    LN_LOAD(0);

    for (int i = 0; i < nch; i++) {
        if (i + 1 < nch) {
            LN_LOAD(i + 1);
            asm volatile("cp.async.wait_group 1;" ::: "memory");
        } else {
            asm volatile("cp.async.wait_group 0;" ::: "memory");
        }
        __syncthreads();

        const uint32_t sAc = sA + (i & 1) * TBYTES;
        const uint32_t sBc = sB + (i & 1) * (256 * TROWB);

#pragma unroll
        for (int ks = 0; ks < 4; ks++) {
            const int kk = ks * 16;
            uint32_t af[4][4];
#pragma unroll
            for (int mt = 0; mt < 4; mt++) {
                const int r = wm * 64 + mt * 16 + gr;
                uint2 a0, a1;
                asm volatile("ld.shared.v2.b32 {%0,%1}, [%2];" : "=r"(a0.x), "=r"(a0.y) : "r"(sAc + swz_frag(r, kk, gc)));
                asm volatile("ld.shared.v2.b32 {%0,%1}, [%2];" : "=r"(a1.x), "=r"(a1.y) : "r"(sAc + swz_frag(r + 8, kk, gc)));
                af[mt][0] = a0.x; af[mt][1] = a1.x; af[mt][2] = a0.y; af[mt][3] = a1.y;
            }
            uint32_t bfr[8][2];
#pragma unroll
            for (int nt = 0; nt < 8; nt++) {
                const int r = wn * 64 + nt * 8 + gr;
                uint2 b0;
                asm volatile("ld.shared.v2.b32 {%0,%1}, [%2];" : "=r"(b0.x), "=r"(b0.y) : "r"(sBc + swz_frag(r, kk, gc)));
                bfr[nt][0] = b0.x; bfr[nt][1] = b0.y;
            }
#pragma unroll
            for (int mt = 0; mt < 4; mt++)
#pragma unroll
                for (int nt = 0; nt < 8; nt++)
                    mma_bf16(acc[mt][nt], af[mt], bfr[nt]);
        }
        __syncthreads();
    }

    // ---- fused bias + residual + LayerNorm ----
    float2* sred = (float2*)sm;          // [128][4] partials

#pragma unroll
    for (int mt = 0; mt < 4; mt++) {
        const int rA = wm * 64 + mt * 16 + gr;
        const int rB = rA + 8;
        float sA2 = 0.f, qA = 0.f, sB2 = 0.f, qB = 0.f;
#pragma unroll
        for (int nt = 0; nt < 8; nt++) {
            const int col = wn * 64 + nt * 8 + gc * 2;
            const float b0 = __ldg(bias + col);
            const float b1 = __ldg(bias + col + 1);
            const float2 rs0 = *(const float2*)(res + (size_t)(row0 + rA) * 256 + col);
            const float2 rs1 = *(const float2*)(res + (size_t)(row0 + rB) * 256 + col);
            acc[mt][nt][0] += b0 + rs0.x;
            acc[mt][nt][1] += b1 + rs0.y;
            acc[mt][nt][2] += b0 + rs1.x;
            acc[mt][nt][3] += b1 + rs1.y;
            sA2 += acc[mt][nt][0] + acc[mt][nt][1];
            qA  += acc[mt][nt][0] * acc[mt][nt][0] + acc[mt][nt][1] * acc[mt][nt][1];
            sB2 += acc[mt][nt][2] + acc[mt][nt][3];
            qB  += acc[mt][nt][2] * acc[mt][nt][2] + acc[mt][nt][3] * acc[mt][nt][3];
        }
#pragma unroll
        for (int o = 1; o <= 2; o <<= 1) {
            sA2 += __shfl_xor_sync(0xffffffffu, sA2, o);
            qA  += __shfl_xor_sync(0xffffffffu, qA,  o);
            sB2 += __shfl_xor_sync(0xffffffffu, sB2, o);
            qB  += __shfl_xor_sync(0xffffffffu, qB,  o);
        }
        if (gc == 0) {
            sred[rA * 4 + wn] = make_float2(sA2, qA);
            sred[rB * 4 + wn] = make_float2(sB2, qB);
        }
    }
    __syncthreads();

#pragma unroll
    for (int mt = 0; mt < 4; mt++) {
        const int rA = wm * 64 + mt * 16 + gr;
        const int rB = rA + 8;
        float2 pA = make_float2(0.f, 0.f), pB = make_float2(0.f, 0.f);
#pragma unroll
        for (int w = 0; w < 4; w++) {
            float2 a = sred[rA * 4 + w]; pA.x += a.x; pA.y += a.y;
            float2 b = sred[rB * 4 + w]; pB.x += b.x; pB.y += b.y;
        }
        const float mA = pA.x * (1.f / 256.f);
        const float vA = fmaxf(pA.y * (1.f / 256.f) - mA * mA, 0.f);
        const float rAst = rsqrtf(vA + LNEPS);
        const float mB = pB.x * (1.f / 256.f);
        const float vB = fmaxf(pB.y * (1.f / 256.f) - mB * mB, 0.f);
        const float rBst = rsqrtf(vB + LNEPS);

#pragma unroll
        for (int nt = 0; nt < 8; nt++) {
            const int col = wn * 64 + nt * 8 + gc * 2;
            const float g0 = __ldg(lng + col),  g1 = __ldg(lng + col + 1);
            const float e0 = __ldg(lnb + col),  e1 = __ldg(lnb + col + 1);
            const float o0 = (acc[mt][nt][0] - mA) * rAst * g0 + e0;
            const float o1 = (acc[mt][nt][1] - mA) * rAst * g1 + e1;
            const float o2 = (acc[mt][nt][2] - mB) * rBst * g0 + e0;
            const float o3 = (acc[mt][nt][3] - mB) * rBst * g1 + e1;
            *(float2*)(Of + (size_t)(row0 + rA) * 256 + col) = make_float2(o0, o1);
            *(float2*)(Of + (size_t)(row0 + rB) * 256 + col) = make_float2(o2, o3);
            if (Ob) {
                const int npi2 = permpair(col >> 1) * 2;
                *(bf162*)(Ob + (size_t)(row0 + rA) * 256 + npi2) = __floats2bfloat162_rn(o0, o1);
                *(bf162*)(Ob + (size_t)(row0 + rB) * 256 + npi2) = __floats2bfloat162_rn(o2, o3);
            }
        }
    }
}

// ---------------------------------------------------------------------------
// Deformable-attention sampling.  One warp per (token, head).
// Operates in the K-permuted channel space (channel-uniform weights).
// ---------------------------------------------------------------------------
__global__ __launch_bounds__(256)
void samp_kernel(const bf16* __restrict__ value, const float* __restrict__ attn,
                 const float* __restrict__ off,  const float* __restrict__ ref,
                 bf16* __restrict__ out)
{
    const int gw   = (blockIdx.x * blockDim.x + threadIdx.x) >> 5;
    const int lane = threadIdx.x & 31;
    if (gw >= MTOK * NHEADS) return;

    const int h    = gw & 7;
    const int bl   = gw >> 3;
    const int b    = (bl >= LEN) ? 1 : 0;
    const int pgrp = lane >> 3;          // point within level
    const int cq   = lane & 7;           // channel quad

    float logit = (lane < 16) ? __ldg(attn + bl * 128 + h * 16 + lane) : -1e30f;
    float m = logit;
#pragma unroll
    for (int o = 16; o > 0; o >>= 1) m = fmaxf(m, __shfl_xor_sync(0xffffffffu, m, o));
    float e = (lane < 16) ? __expf(logit - m) : 0.f;
    float s = e;
#pragma unroll
    for (int o = 16; o > 0; o >>= 1) s += __shfl_xor_sync(0xffffffffu, s, o);
    const float wn = e / s;

    const float ov = __ldg(off + bl * 256 + h * 32 + lane);
    const float rv = (lane < 8) ? __ldg(ref + bl * 8 + lane) : 0.f;

    const int Hs[4] = {128, 64, 32, 16};
    const int Ss[4] = {0, 16384, 20480, 21504};

    float4 acc4 = make_float4(0.f, 0.f, 0.f, 0.f);
#pragma unroll
    for (int l = 0; l < 4; l++) {
        const int   Wl = Hs[l];
        const float fW = (float)Wl;
        const float rx = __shfl_sync(0xffffffffu, rv, 2 * l);
        const float ry = __shfl_sync(0xffffffffu, rv, 2 * l + 1);
        const uint2* vb = (const uint2*)(value + (size_t)(b * LEN + Ss[l]) * 256 + h * 32) + cq;

        const float ox = __shfl_sync(0xffffffffu, ov, l * 8 + pgrp * 2);
        const float oy = __shfl_sync(0xffffffffu, ov, l * 8 + pgrp * 2 + 1);
        const float aw = __shfl_sync(0xffffffffu, wn, l * 4 + pgrp);
        const float x  = fmaf(rx, fW, ox) - 0.5f;
        const float y  = fmaf(ry, fW, oy) - 0.5f;
        const float x0f = floorf(x), y0f = floorf(y);
        const float dx = x - x0f, dy = y - y0f;
        const int   x0 = (int)x0f, y0 = (int)y0f;

        float4 psum = make_float4(0.f, 0.f, 0.f, 0.f);
#pragma unroll
        for (int c = 0; c < 4; c++) {
            const int xi = x0 + (c & 1);
            const int yi = y0 + (c >> 1);
            const float cw = ((c & 1) ? dx : 1.f - dx) * ((c >> 1) ? dy : 1.f - dy);
            const bool valid = (xi >= 0) & (xi < Wl) & (yi >= 0) & (yi < Wl);
            const int xc = min(max(xi, 0), Wl - 1);
            const int yc = min(max(yi, 0), Wl - 1);
            const uint2 raw = vb[(size_t)(yc * Wl + xc) * 64];
            const float2 v0 = __bfloat1622float2(*(const bf162*)&raw.x);
            const float2 v1 = __bfloat1622float2(*(const bf162*)&raw.y);
            const float w = valid ? cw : 0.f;
            psum.x = fmaf(v0.x, w, psum.x);
            psum.y = fmaf(v0.y, w, psum.y);
            psum.z = fmaf(v1.x, w, psum.z);
            psum.w = fmaf(v1.y, w, psum.w);
        }
        acc4.x = fmaf(aw, psum.x, acc4.x);
        acc4.y = fmaf(aw, psum.y, acc4.y);
        acc4.z = fmaf(aw, psum.z, acc4.z);
        acc4.w = fmaf(aw, psum.w, acc4.w);
    }
#pragma unroll
    for (int o = 8; o <= 16; o <<= 1) {
        acc4.x += __shfl_xor_sync(0xffffffffu, acc4.x, o);
        acc4.y += __shfl_xor_sync(0xffffffffu, acc4.y, o);
        acc4.z += __shfl_xor_sync(0xffffffffu, acc4.z, o);
        acc4.w += __shfl_xor_sync(0xffffffffu, acc4.w, o);
    }
    if (pgrp == 0) {
        uint2 packed;
        bf162 p0 = __floats2bfloat162_rn(acc4.x, acc4.y);
        bf162 p1 = __floats2bfloat162_rn(acc4.z, acc4.w);
        packed.x = *(const uint32_t*)&p0;
        packed.y = *(const uint32_t*)&p1;
        ((uint2*)(out + (size_t)bl * 256 + h * 32))[cq] = packed;
    }
}

// ---------------------------------------------------------------------------
// Launch
// ---------------------------------------------------------------------------
extern "C" void kernel_launch(void* const* d_in, const int* in_sizes, int n_in,
                              void* d_out, int out_size)
{
    const float* src  = (const float*)d_in[0];
    const float* pos  = (const float*)d_in[1];
    const float* ref  = (const float*)d_in[2];
    const unsigned char* mask = (const unsigned char*)d_in[5];
    const float* w_off  = (const float*)d_in[6];
    const float* b_off  = (const float*)d_in[7];
    const float* w_attn = (const float*)d_in[8];
    const float* b_attn = (const float*)d_in[9];
    const float* w_val  = (const float*)d_in[10];
    const float* b_val  = (const float*)d_in[11];
    const float* w_out  = (const float*)d_in[12];
    const float* b_out  = (const float*)d_in[13];
    const float* ln1g   = (const float*)d_in[14];
    const float* ln1b   = (const float*)d_in[15];
    const float* w1     = (const float*)d_in[16];
    const float* b1     = (const float*)d_in[17];
    const float* w2     = (const float*)d_in[18];
    const float* b2     = (const float*)d_in[19];
    const float* ln2g   = (const float*)d_in[20];
    const float* ln2b   = (const float*)d_in[21];
    float* out = (float*)d_out;

    bf16 *p_srcb, *p_qb, *p_value, *p_samp, *p_xb, *p_h;
    float *p_off, *p_attn, *p_x;
    bf16 *t_val, *t_offat, *t_out, *t_w1, *t_w2;
    cudaGetSymbolAddress((void**)&p_srcb,  g_srcb);
    cudaGetSymbolAddress((void**)&p_qb,    g_qb);
    cudaGetSymbolAddress((void**)&p_value, g_value);
    cudaGetSymbolAddress((void**)&p_off,   g_off);
    cudaGetSymbolAddress((void**)&p_attn,  g_attn);
    cudaGetSymbolAddress((void**)&p_samp,  g_samp);
    cudaGetSymbolAddress((void**)&p_x,     g_x);
    cudaGetSymbolAddress((void**)&p_xb,    g_xb);
    cudaGetSymbolAddress((void**)&p_h,     g_h);
    cudaGetSymbolAddress((void**)&t_val,   g_wtval);
    cudaGetSymbolAddress((void**)&t_offat, g_wtoffat);
    cudaGetSymbolAddress((void**)&t_out,   g_wtout);
    cudaGetSymbolAddress((void**)&t_w1,    g_wt1);
    cudaGetSymbolAddress((void**)&t_w2,    g_wt2);

    const int SMEM   = 4 * TBYTES;                       // 65536
    const int SMEMLN = 2 * TBYTES + 2 * 256 * TROWB;     // 98304
    cudaFuncSetAttribute(gemm_bf, cudaFuncAttributeMaxDynamicSharedMemorySize, SMEM);
    cudaFuncSetAttribute(gemm_ln, cudaFuncAttributeMaxDynamicSharedMemorySize, SMEMLN);

    const int MY = MTOK / 128;   // 340

    // 1. srcb = bf16(src); qb = bf16(src + pos)   (K-permuted)
    prep_kernel<<<(MTOK * 256 / 4 + 255) / 256, 256>>>(src, pos, p_srcb, p_qb, MTOK * 256 / 4);

    // 2. all weight transposes in one launch (K-permuted)
    TSeg s0 = { w_val,  t_val,   256, 256,   0,   0 };
    TSeg s1 = { w_off,  t_offat, 256, 256,  64,   0 };
    TSeg s2 = { w_attn, t_offat, 256, 128, 128, 256 };
    TSeg s3 = { w_out,  t_out,   256, 256, 160,   0 };
    TSeg s4 = { w1,     t_w1,    256, 1024, 224,  0 };
    TSeg s5 = { w2,     t_w2,    1024, 256, 480,  0 };
    transpose_all<<<736, dim3(32, 8)>>>(s0, s1, s2, s3, s4, s5);

    // 3. value = srcb @ w_val + b_val (masked), bf16 out (permuted)
    gemm_bf<<<dim3(2, MY), 128, SMEM>>>(p_srcb, t_val, b_val, nullptr, mask,
                                        nullptr, nullptr, p_value, 256, 256, 0, -1, 0);
    // 4. [off | attn] = qb @ t_offat  (split epilogue, fp32 unpermuted)
    gemm_bf<<<dim3(3, MY), 128, SMEM>>>(p_qb, t_offat, b_off, b_attn, nullptr,
                                        p_off, p_attn, nullptr, 256, 256, 128, 256, 0);
    // 5. deformable sampling (permuted in/out)
    samp_kernel<<<(MTOK * NHEADS) / 8, 256>>>(p_value, p_attn, p_off, ref, p_samp);
    // 6. x = LN(src + samp @ w_out + b_out)  -> fp32 (unperm) + bf16 (perm)
    gemm_ln<<<dim3(1, MY), 256, SMEMLN>>>(p_samp, t_out, b_out, src, ln1g, ln1b, p_x, p_xb, 256);
    // 7. h = relu(xb @ w1 + b1), bf16 out (permuted)
    gemm_bf<<<dim3(8, MY), 128, SMEM>>>(p_xb, t_w1, b1, nullptr, nullptr,
                                        nullptr, nullptr, p_h, 256, 1024, 0, -1, 1);
    // 8. out = LN(x + h @ w2 + b2)  (fp32 unpermuted)
    gemm_ln<<<dim3(1, MY), 256, SMEMLN>>>(p_h, t_w2, b2, p_x, ln2g, ln2b, out, nullptr, 1024);
}

// round 16
// speedup vs baseline: 1.0630x; 1.0111x over previous
#include <cuda_runtime.h>
#include <cuda_bf16.h>
#include <cstdint>
#include <math.h>

// Problem constants (fixed by the dataset)
#define LEN    21760
#define BATCH  2
#define MTOK   (BATCH * LEN)          // 43520
#define DMODEL 256
#define DFFN   1024
#define NHEADS 8
#define LNEPS  1e-5f

typedef __nv_bfloat16 bf16;
typedef __nv_bfloat162 bf162;

// K-permutation within each 16-element group: [0,1,8,9,2,3,10,11,4,5,12,13,6,7,14,15]
__host__ __device__ __forceinline__ int permk(int k) {
    return (k & ~15) | (((k >> 1) & 3) << 2) | (((k >> 3) & 1) << 1) | (k & 1);
}
__device__ __forceinline__ int permpair(int pi) {
    return (pi & ~7) | ((pi & 3) << 1) | ((pi >> 2) & 1);
}

// ---------------------------------------------------------------------------
// Scratch (device globals — no allocation).  bf16 activations K-permuted.
// ---------------------------------------------------------------------------
__device__ bf16  g_srcb [(size_t)MTOK * DMODEL];
__device__ bf16  g_qb   [(size_t)MTOK * DMODEL];
__device__ bf16  g_value[(size_t)MTOK * DMODEL];
__device__ float g_off  [(size_t)MTOK * DMODEL];
__device__ float g_attn [(size_t)MTOK * 128];
__device__ bf16  g_samp [(size_t)MTOK * DMODEL];
__device__ float g_x    [(size_t)MTOK * DMODEL];
__device__ bf16  g_xb   [(size_t)MTOK * DMODEL];
__device__ bf16  g_h    [(size_t)MTOK * DFFN];
// transposed bf16 weights [N, K] (K-major, K permuted)
__device__ bf16 g_wtval   [256 * 256];
__device__ bf16 g_wtoffat [384 * 256];
__device__ bf16 g_wtout   [256 * 256];
__device__ bf16 g_wt1     [1024 * 256];
__device__ bf16 g_wt2     [256 * 1024];

// ---------------------------------------------------------------------------
// Helpers
// ---------------------------------------------------------------------------
__device__ __forceinline__ uint32_t smem_u32(const void* p) {
    uint32_t a;
    asm("{ .reg .u64 t; cvta.to.shared.u64 t, %1; cvt.u32.u64 %0, t; }" : "=r"(a) : "l"(p));
    return a;
}
__device__ __forceinline__ void cp_async16(uint32_t saddr, const void* gaddr) {
    asm volatile("cp.async.cg.shared.global [%0], [%1], 16;" :: "r"(saddr), "l"(gaddr));
}
__device__ __forceinline__ void cp_commit() { asm volatile("cp.async.commit_group;"); }

__device__ __forceinline__ void mma_bf16(float* d, const uint32_t* a, const uint32_t* b) {
    asm volatile(
        "mma.sync.aligned.m16n8k16.row.col.f32.bf16.bf16.f32 "
        "{%0,%1,%2,%3}, {%4,%5,%6,%7}, {%8,%9}, {%0,%1,%2,%3};"
        : "+f"(d[0]), "+f"(d[1]), "+f"(d[2]), "+f"(d[3])
        : "r"(a[0]), "r"(a[1]), "r"(a[2]), "r"(a[3]), "r"(b[0]), "r"(b[1]));
}

// Swizzled smem addressing: rows of 128B (64 bf16), 16B chunks, chunk XOR (row&3)<<1.
__device__ __forceinline__ uint32_t swz_store(int row, int c) {
    return (uint32_t)(row * 128 + ((c ^ ((row & 3) << 1)) << 4));
}
__device__ __forceinline__ uint32_t swz_frag(int r, int kk, int gc) {
    const int chunk = (kk >> 3) + (gc >> 1);
    return (uint32_t)(r * 128 + ((chunk ^ ((r & 3) << 1)) << 4) + ((gc & 1) << 3));
}

// ---------------------------------------------------------------------------
// prep: srcb = bf16(src), qb = bf16(src + pos)   (K-permuted)
// ---------------------------------------------------------------------------
__global__ __launch_bounds__(256)
void prep_kernel(const float* __restrict__ src, const float* __restrict__ pos,
                 bf16* __restrict__ srcb, bf16* __restrict__ qb, int n4)
{
    const int i = blockIdx.x * blockDim.x + threadIdx.x;
    if (i >= n4) return;
    float4 s = ((const float4*)src)[i];
    float4 p = ((const float4*)pos)[i];
    const int pi0 = permpair(2 * i);
    const int pi1 = permpair(2 * i + 1);
    ((bf162*)srcb)[pi0] = __floats2bfloat162_rn(s.x, s.y);
    ((bf162*)srcb)[pi1] = __floats2bfloat162_rn(s.z, s.w);
    ((bf162*)qb)[pi0] = __floats2bfloat162_rn(s.x + p.x, s.y + p.y);
    ((bf162*)qb)[pi1] = __floats2bfloat162_rn(s.z + p.z, s.w + p.w);
}

// ---------------------------------------------------------------------------
// All weight transposes in ONE launch. out[(rowOff+n)*K + permk(k)] = bf16(in[k*N+n])
// ---------------------------------------------------------------------------
struct TSeg { const float* in; bf16* out; int K, N, start, rowOff; };

__global__ void transpose_all(TSeg s0, TSeg s1, TSeg s2, TSeg s3, TSeg s4, TSeg s5)
{
    TSeg s;
    const int b = blockIdx.x;
    if      (b < s1.start) s = s0;
    else if (b < s2.start) s = s1;
    else if (b < s3.start) s = s2;
    else if (b < s4.start) s = s3;
    else if (b < s5.start) s = s4;
    else                   s = s5;

    const int local = b - s.start;
    const int tx_n  = s.N / 32;
    const int n0 = (local % tx_n) * 32;
    const int k0 = (local / tx_n) * 32;

    __shared__ float t[32][33];
    const int tx = threadIdx.x, ty = threadIdx.y;
#pragma unroll
    for (int j = 0; j < 32; j += 8)
        t[ty + j][tx] = s.in[(size_t)(k0 + ty + j) * s.N + n0 + tx];
    __syncthreads();
#pragma unroll
    for (int j = 0; j < 32; j += 8)
        s.out[(size_t)(s.rowOff + n0 + ty + j) * s.K + permk(k0 + tx)] = __float2bfloat16(t[tx][ty + j]);
}

// ---------------------------------------------------------------------------
// bf16 mma GEMM.  BM=BN=128, BK=64.  128 threads, 4 warps (2x2), warp 64x64.
// K-permuted + swizzled smem, 3-stage cp.async pipeline.  2 CTAs/SM (no spill).
// Smem: 3 x (128+128) rows x 128B = 96 KB.
// ---------------------------------------------------------------------------
#define TROWB 128                     // bytes per smem row
#define TBYTES (128 * TROWB)          // one tile buffer (128 rows)

__global__ __launch_bounds__(128, 2)
void gemm_bf(const bf16* __restrict__ A, const bf16* __restrict__ BT,
             const float* __restrict__ bias, const float* __restrict__ bias2,
             const unsigned char* __restrict__ mask,
             float* __restrict__ Cf, float* __restrict__ Cf2, bf16* __restrict__ Cb,
             int K, int N, int N2, int splitCol, int relu)
{
    extern __shared__ bf16 sm[];
    const uint32_t sA = smem_u32(sm);
    const uint32_t sB = sA + 3 * TBYTES;

    const int tid  = threadIdx.x;
    const int wid  = tid >> 5;
    const int lane = tid & 31;
    const int gr   = lane >> 2;
    const int gc   = lane & 3;
    const int wm   = wid & 1;          // row half (64)
    const int wn   = wid >> 1;         // col half (64)
    const int row0 = blockIdx.y * 128;
    const int col0 = blockIdx.x * 128;

    float acc[4][8][4];
#pragma unroll
    for (int mt = 0; mt < 4; mt++)
#pragma unroll
        for (int nt = 0; nt < 8; nt++)
#pragma unroll
            for (int r = 0; r < 4; r++) acc[mt][nt][r] = 0.f;

    const int nch = K >> 6;
    const int lrow = tid >> 3;          // 0..15
    const int lchk = tid & 7;           // chunk 0..7
    const int lc   = lchk << 3;         // element offset

    const bf16* Ab = A  + (size_t)(row0 + lrow) * K + lc;
    const bf16* Bb = BT + (size_t)(col0 + lrow) * K + lc;

#define LOAD_CHUNK(i) do {                                                        \
        const int _k0 = (i) << 6;                                                 \
        const uint32_t _abase = sA + ((i) % 3) * TBYTES;                          \
        const uint32_t _bbase = sB + ((i) % 3) * TBYTES;                          \
        _Pragma("unroll")                                                         \
        for (int it = 0; it < 8; it++) {                                          \
            const int r = lrow + it * 16;                                         \
            cp_async16(_abase + swz_store(r, lchk), Ab + (size_t)(it * 16) * K + _k0); \
            cp_async16(_bbase + swz_store(r, lchk), Bb + (size_t)(it * 16) * K + _k0); \
        }                                                                         \
        cp_commit();                                                              \
    } while (0)

    LOAD_CHUNK(0);
    if (nch > 1) LOAD_CHUNK(1);

    for (int i = 0; i < nch; i++) {
        if (i + 2 < nch) {
            LOAD_CHUNK(i + 2);
            asm volatile("cp.async.wait_group 2;" ::: "memory");
        } else if (i + 1 < nch) {
            asm volatile("cp.async.wait_group 1;" ::: "memory");
        } else {
            asm volatile("cp.async.wait_group 0;" ::: "memory");
        }
        __syncthreads();

        const uint32_t sAc = sA + (i % 3) * TBYTES;
        const uint32_t sBc = sB + (i % 3) * TBYTES;

#pragma unroll
        for (int ks = 0; ks < 4; ks++) {
            const int kk = ks * 16;
            uint32_t af[4][4];
#pragma unroll
            for (int mt = 0; mt < 4; mt++) {
                const int r = wm * 64 + mt * 16 + gr;
                uint2 a0, a1;
                asm volatile("ld.shared.v2.b32 {%0,%1}, [%2];" : "=r"(a0.x), "=r"(a0.y) : "r"(sAc + swz_frag(r, kk, gc)));
                asm volatile("ld.shared.v2.b32 {%0,%1}, [%2];" : "=r"(a1.x), "=r"(a1.y) : "r"(sAc + swz_frag(r + 8, kk, gc)));
                af[mt][0] = a0.x; af[mt][1] = a1.x; af[mt][2] = a0.y; af[mt][3] = a1.y;
            }
            uint32_t bfr[8][2];
#pragma unroll
            for (int nt = 0; nt < 8; nt++) {
                const int r = wn * 64 + nt * 8 + gr;
                uint2 b0;
                asm volatile("ld.shared.v2.b32 {%0,%1}, [%2];" : "=r"(b0.x), "=r"(b0.y) : "r"(sBc + swz_frag(r, kk, gc)));
                bfr[nt][0] = b0.x; bfr[nt][1] = b0.y;
            }
#pragma unroll
            for (int mt = 0; mt < 4; mt++)
#pragma unroll
                for (int nt = 0; nt < 8; nt++)
                    mma_bf16(acc[mt][nt], af[mt], bfr[nt]);
        }
        __syncthreads();
    }

    const bool second = (splitCol >= 0) && (col0 >= splitCol);
    const float* biasP = second ? bias2 : bias;
    float* CfP = second ? Cf2 : Cf;
    const int  Nout  = second ? N2 : N;
    const int  cbase = second ? col0 - splitCol : col0;

#pragma unroll
    for (int mt = 0; mt < 4; mt++) {
        const int r0 = row0 + wm * 64 + mt * 16 + gr;
        const bool m0 = mask && mask[r0];
        const bool m1 = mask && mask[r0 + 8];
#pragma unroll
        for (int nt = 0; nt < 8; nt++) {
            const int col = cbase + wn * 64 + nt * 8 + gc * 2;
            const float b0 = __ldg(biasP + col);
            const float b1 = __ldg(biasP + col + 1);
            float v0 = acc[mt][nt][0] + b0, v1 = acc[mt][nt][1] + b1;
            float v2 = acc[mt][nt][2] + b0, v3 = acc[mt][nt][3] + b1;
            if (relu) {
                v0 = fmaxf(v0, 0.f); v1 = fmaxf(v1, 0.f);
                v2 = fmaxf(v2, 0.f); v3 = fmaxf(v3, 0.f);
            }
            if (m0) { v0 = v1 = 0.f; }
            if (m1) { v2 = v3 = 0.f; }
            if (CfP) {
                *(float2*)(CfP + (size_t)r0 * Nout + col)       = make_float2(v0, v1);
                *(float2*)(CfP + (size_t)(r0 + 8) * Nout + col) = make_float2(v2, v3);
            }
            if (Cb) {
                const int npi2 = permpair(col >> 1) * 2;
                *(bf162*)(Cb + (size_t)r0 * Nout + npi2)       = __floats2bfloat162_rn(v0, v1);
                *(bf162*)(Cb + (size_t)(r0 + 8) * Nout + npi2) = __floats2bfloat162_rn(v2, v3);
            }
        }
    }
}

// ---------------------------------------------------------------------------
// GEMM + bias + residual + LayerNorm fused.  N = 256 (full row per CTA).
// BM=128, BN=256, 256 threads (8 warps 2x4), warp tile 64x64, swizzled smem,
// 3-stage pipeline.  Smem: 3 x (128+256) rows x 128B = 144 KB.
// ---------------------------------------------------------------------------
__global__ __launch_bounds__(256, 1)
void gemm_ln(const bf16* __restrict__ A, const bf16* __restrict__ BT,
             const float* __restrict__ bias, const float* __restrict__ res,
             const float* __restrict__ lng, const float* __restrict__ lnb,
             float* __restrict__ Of, bf16* __restrict__ Ob, int K)
{
    extern __shared__ bf16 sm[];
    const uint32_t sA = smem_u32(sm);                 // 3 x 128 rows
    const uint32_t sB = sA + 3 * TBYTES;              // 3 x 256 rows

    const int tid  = threadIdx.x;
    const int wid  = tid >> 5;
    const int lane = tid & 31;
    const int gr   = lane >> 2;
    const int gc   = lane & 3;
    const int wm   = wid & 1;            // row half (64)
    const int wn   = wid >> 1;           // col quarter (64)
    const int row0 = blockIdx.y * 128;

    float acc[4][8][4];
#pragma unroll
    for (int mt = 0; mt < 4; mt++)
#pragma unroll
        for (int nt = 0; nt < 8; nt++)
#pragma unroll
            for (int r = 0; r < 4; r++) acc[mt][nt][r] = 0.f;

    const int nch = K >> 6;
    const int lrow = tid >> 3;           // 0..31
    const int lchk = tid & 7;
    const int lc   = lchk << 3;

#define LN_LOAD(i) do {                                                            \
        const int _k0 = (i) << 6;                                                  \
        const uint32_t _ab = sA + ((i) % 3) * TBYTES;                              \
        const uint32_t _bb = sB + ((i) % 3) * (256 * TROWB);                       \
        _Pragma("unroll")                                                          \
        for (int it = 0; it < 4; it++) {                                           \
            const int r = lrow + it * 32;                                          \
            cp_async16(_ab + swz_store(r, lchk),                                   \
                       A + (size_t)(row0 + r) * K + lc + _k0);                     \
        }                                                                          \
        _Pragma("unroll")                                                          \
        for (int it = 0; it < 8; it++) {                                           \
            const int r = lrow + it * 32;                                          \
            cp_async16(_bb + swz_store(r, lchk),                                   \
                       BT + (size_t)r * K + lc + _k0);                             \
        }                                                                          \
        cp_commit();                                                               \
    } while (0)

    LN_LOAD(0);
    if (nch > 1) LN_LOAD(1);

    for (int i = 0; i < nch; i++) {
        if (i + 2 < nch) {
            LN_LOAD(i + 2);
            asm volatile("cp.async.wait_group 2;" ::: "memory");
        } else if (i + 1 < nch) {
            asm volatile("cp.async.wait_group 1;" ::: "memory");
        } else {
            asm volatile("cp.async.wait_group 0;" ::: "memory");
        }
        __syncthreads();

        const uint32_t sAc = sA + (i % 3) * TBYTES;
        const uint32_t sBc = sB + (i % 3) * (256 * TROWB);

#pragma unroll
        for (int ks = 0; ks < 4; ks++) {
            const int kk = ks * 16;
            uint32_t af[4][4];
#pragma unroll
            for (int mt = 0; mt < 4; mt++) {
                const int r = wm * 64 + mt * 16 + gr;
                uint2 a0, a1;
                asm volatile("ld.shared.v2.b32 {%0,%1}, [%2];" : "=r"(a0.x), "=r"(a0.y) : "r"(sAc + swz_frag(r, kk, gc)));
                asm volatile("ld.shared.v2.b32 {%0,%1}, [%2];" : "=r"(a1.x), "=r"(a1.y) : "r"(sAc + swz_frag(r + 8, kk, gc)));
                af[mt][0] = a0.x; af[mt][1] = a1.x; af[mt][2] = a0.y; af[mt][3] = a1.y;
            }
            uint32_t bfr[8][2];
#pragma unroll
            for (int nt = 0; nt < 8; nt++) {
                const int r = wn * 64 + nt * 8 + gr;
                uint2 b0;
                asm volatile("ld.shared.v2.b32 {%0,%1}, [%2];" : "=r"(b0.x), "=r"(b0.y) : "r"(sBc + swz_frag(r, kk, gc)));
                bfr[nt][0] = b0.x; bfr[nt][1] = b0.y;
            }
#pragma unroll
            for (int mt = 0; mt < 4; mt++)
#pragma unroll
                for (int nt = 0; nt < 8; nt++)
                    mma_bf16(acc[mt][nt], af[mt], bfr[nt]);
        }
        __syncthreads();
    }

    // ---- fused bias + residual + LayerNorm ----
    float2* sred = (float2*)sm;          // [128][4] partials

#pragma unroll
    for (int mt = 0; mt < 4; mt++) {
        const int rA = wm * 64 + mt * 16 + gr;
        const int rB = rA + 8;
        float sA2 = 0.f, qA = 0.f, sB2 = 0.f, qB = 0.f;
#pragma unroll
        for (int nt = 0; nt < 8; nt++) {
            const int col = wn * 64 + nt * 8 + gc * 2;
            const float b0 = __ldg(bias + col);
            const float b1 = __ldg(bias + col + 1);
            const float2 rs0 = *(const float2*)(res + (size_t)(row0 + rA) * 256 + col);
            const float2 rs1 = *(const float2*)(res + (size_t)(row0 + rB) * 256 + col);
            acc[mt][nt][0] += b0 + rs0.x;
            acc[mt][nt][1] += b1 + rs0.y;
            acc[mt][nt][2] += b0 + rs1.x;
            acc[mt][nt][3] += b1 + rs1.y;
            sA2 += acc[mt][nt][0] + acc[mt][nt][1];
            qA  += acc[mt][nt][0] * acc[mt][nt][0] + acc[mt][nt][1] * acc[mt][nt][1];
            sB2 += acc[mt][nt][2] + acc[mt][nt][3];
            qB  += acc[mt][nt][2] * acc[mt][nt][2] + acc[mt][nt][3] * acc[mt][nt][3];
        }
#pragma unroll
        for (int o = 1; o <= 2; o <<= 1) {
            sA2 += __shfl_xor_sync(0xffffffffu, sA2, o);
            qA  += __shfl_xor_sync(0xffffffffu, qA,  o);
            sB2 += __shfl_xor_sync(0xffffffffu, sB2, o);
            qB  += __shfl_xor_sync(0xffffffffu, qB,  o);
        }
        if (gc == 0) {
            sred[rA * 4 + wn] = make_float2(sA2, qA);
            sred[rB * 4 + wn] = make_float2(sB2, qB);
        }
    }
    __syncthreads();

#pragma unroll
    for (int mt = 0; mt < 4; mt++) {
        const int rA = wm * 64 + mt * 16 + gr;
        const int rB = rA + 8;
        float2 pA = make_float2(0.f, 0.f), pB = make_float2(0.f, 0.f);
#pragma unroll
        for (int w = 0; w < 4; w++) {
            float2 a = sred[rA * 4 + w]; pA.x += a.x; pA.y += a.y;
            float2 b = sred[rB * 4 + w]; pB.x += b.x; pB.y += b.y;
        }
        const float mA = pA.x * (1.f / 256.f);
        const float vA = fmaxf(pA.y * (1.f / 256.f) - mA * mA, 0.f);
        const float rAst = rsqrtf(vA + LNEPS);
        const float mB = pB.x * (1.f / 256.f);
        const float vB = fmaxf(pB.y * (1.f / 256.f) - mB * mB, 0.f);
        const float rBst = rsqrtf(vB + LNEPS);

#pragma unroll
        for (int nt = 0; nt < 8; nt++) {
            const int col = wn * 64 + nt * 8 + gc * 2;
            const float g0 = __ldg(lng + col),  g1 = __ldg(lng + col + 1);
            const float e0 = __ldg(lnb + col),  e1 = __ldg(lnb + col + 1);
            const float o0 = (acc[mt][nt][0] - mA) * rAst * g0 + e0;
            const float o1 = (acc[mt][nt][1] - mA) * rAst * g1 + e1;
            const float o2 = (acc[mt][nt][2] - mB) * rBst * g0 + e0;
            const float o3 = (acc[mt][nt][3] - mB) * rBst * g1 + e1;
            *(float2*)(Of + (size_t)(row0 + rA) * 256 + col) = make_float2(o0, o1);
            *(float2*)(Of + (size_t)(row0 + rB) * 256 + col) = make_float2(o2, o3);
            if (Ob) {
                const int npi2 = permpair(col >> 1) * 2;
                *(bf162*)(Ob + (size_t)(row0 + rA) * 256 + npi2) = __floats2bfloat162_rn(o0, o1);
                *(bf162*)(Ob + (size_t)(row0 + rB) * 256 + npi2) = __floats2bfloat162_rn(o2, o3);
            }
        }
    }
}

// ---------------------------------------------------------------------------
// Deformable-attention sampling.  One warp per (token, head).
// Operates in the K-permuted channel space (channel-uniform weights).
// ---------------------------------------------------------------------------
__global__ __launch_bounds__(256)
void samp_kernel(const bf16* __restrict__ value, const float* __restrict__ attn,
                 const float* __restrict__ off,  const float* __restrict__ ref,
                 bf16* __restrict__ out)
{
    const int gw   = (blockIdx.x * blockDim.x + threadIdx.x) >> 5;
    const int lane = threadIdx.x & 31;
    if (gw >= MTOK * NHEADS) return;

    const int h    = gw & 7;
    const int bl   = gw >> 3;
    const int b    = (bl >= LEN) ? 1 : 0;
    const int pgrp = lane >> 3;          // point within level
    const int cq   = lane & 7;           // channel quad

    float logit = (lane < 16) ? __ldg(attn + bl * 128 + h * 16 + lane) : -1e30f;
    float m = logit;
#pragma unroll
    for (int o = 16; o > 0; o >>= 1) m = fmaxf(m, __shfl_xor_sync(0xffffffffu, m, o));
    float e = (lane < 16) ? __expf(logit - m) : 0.f;
    float s = e;
#pragma unroll
    for (int o = 16; o > 0; o >>= 1) s += __shfl_xor_sync(0xffffffffu, s, o);
    const float wn = e / s;

    const float ov = __ldg(off + bl * 256 + h * 32 + lane);
    const float rv = (lane < 8) ? __ldg(ref + bl * 8 + lane) : 0.f;

    const int Hs[4] = {128, 64, 32, 16};
    const int Ss[4] = {0, 16384, 20480, 21504};

    float4 acc4 = make_float4(0.f, 0.f, 0.f, 0.f);
#pragma unroll
    for (int l = 0; l < 4; l++) {
        const int   Wl = Hs[l];
        const float fW = (float)Wl;
        const float rx = __shfl_sync(0xffffffffu, rv, 2 * l);
        const float ry = __shfl_sync(0xffffffffu, rv, 2 * l + 1);
        const uint2* vb = (const uint2*)(value + (size_t)(b * LEN + Ss[l]) * 256 + h * 32) + cq;

        const float ox = __shfl_sync(0xffffffffu, ov, l * 8 + pgrp * 2);
        const float oy = __shfl_sync(0xffffffffu, ov, l * 8 + pgrp * 2 + 1);
        const float aw = __shfl_sync(0xffffffffu, wn, l * 4 + pgrp);
        const float x  = fmaf(rx, fW, ox) - 0.5f;
        const float y  = fmaf(ry, fW, oy) - 0.5f;
        const float x0f = floorf(x), y0f = floorf(y);
        const float dx = x - x0f, dy = y - y0f;
        const int   x0 = (int)x0f, y0 = (int)y0f;

        float4 psum = make_float4(0.f, 0.f, 0.f, 0.f);
#pragma unroll
        for (int c = 0; c < 4; c++) {
            const int xi = x0 + (c & 1);
            const int yi = y0 + (c >> 1);
            const float cw = ((c & 1) ? dx : 1.f - dx) * ((c >> 1) ? dy : 1.f - dy);
            const bool valid = (xi >= 0) & (xi < Wl) & (yi >= 0) & (yi < Wl);
            const int xc = min(max(xi, 0), Wl - 1);
            const int yc = min(max(yi, 0), Wl - 1);
            const uint2 raw = vb[(size_t)(yc * Wl + xc) * 64];
            const float2 v0 = __bfloat1622float2(*(const bf162*)&raw.x);
            const float2 v1 = __bfloat1622float2(*(const bf162*)&raw.y);
            const float w = valid ? cw : 0.f;
            psum.x = fmaf(v0.x, w, psum.x);
            psum.y = fmaf(v0.y, w, psum.y);
            psum.z = fmaf(v1.x, w, psum.z);
            psum.w = fmaf(v1.y, w, psum.w);
        }
        acc4.x = fmaf(aw, psum.x, acc4.x);
        acc4.y = fmaf(aw, psum.y, acc4.y);
        acc4.z = fmaf(aw, psum.z, acc4.z);
        acc4.w = fmaf(aw, psum.w, acc4.w);
    }
#pragma unroll
    for (int o = 8; o <= 16; o <<= 1) {
        acc4.x += __shfl_xor_sync(0xffffffffu, acc4.x, o);
        acc4.y += __shfl_xor_sync(0xffffffffu, acc4.y, o);
        acc4.z += __shfl_xor_sync(0xffffffffu, acc4.z, o);
        acc4.w += __shfl_xor_sync(0xffffffffu, acc4.w, o);
    }
    if (pgrp == 0) {
        uint2 packed;
        bf162 p0 = __floats2bfloat162_rn(acc4.x, acc4.y);
        bf162 p1 = __floats2bfloat162_rn(acc4.z, acc4.w);
        packed.x = *(const uint32_t*)&p0;
        packed.y = *(const uint32_t*)&p1;
        ((uint2*)(out + (size_t)bl * 256 + h * 32))[cq] = packed;
    }
}

// ---------------------------------------------------------------------------
// Launch
// ---------------------------------------------------------------------------
extern "C" void kernel_launch(void* const* d_in, const int* in_sizes, int n_in,
                              void* d_out, int out_size)
{
    const float* src  = (const float*)d_in[0];
    const float* pos  = (const float*)d_in[1];
    const float* ref  = (const float*)d_in[2];
    const unsigned char* mask = (const unsigned char*)d_in[5];
    const float* w_off  = (const float*)d_in[6];
    const float* b_off  = (const float*)d_in[7];
    const float* w_attn = (const float*)d_in[8];
    const float* b_attn = (const float*)d_in[9];
    const float* w_val  = (const float*)d_in[10];
    const float* b_val  = (const float*)d_in[11];
    const float* w_out  = (const float*)d_in[12];
    const float* b_out  = (const float*)d_in[13];
    const float* ln1g   = (const float*)d_in[14];
    const float* ln1b   = (const float*)d_in[15];
    const float* w1     = (const float*)d_in[16];
    const float* b1     = (const float*)d_in[17];
    const float* w2     = (const float*)d_in[18];
    const float* b2     = (const float*)d_in[19];
    const float* ln2g   = (const float*)d_in[20];
    const float* ln2b   = (const float*)d_in[21];
    float* out = (float*)d_out;

    bf16 *p_srcb, *p_qb, *p_value, *p_samp, *p_xb, *p_h;
    float *p_off, *p_attn, *p_x;
    bf16 *t_val, *t_offat, *t_out, *t_w1, *t_w2;
    cudaGetSymbolAddress((void**)&p_srcb,  g_srcb);
    cudaGetSymbolAddress((void**)&p_qb,    g_qb);
    cudaGetSymbolAddress((void**)&p_value, g_value);
    cudaGetSymbolAddress((void**)&p_off,   g_off);
    cudaGetSymbolAddress((void**)&p_attn,  g_attn);
    cudaGetSymbolAddress((void**)&p_samp,  g_samp);
    cudaGetSymbolAddress((void**)&p_x,     g_x);
    cudaGetSymbolAddress((void**)&p_xb,    g_xb);
    cudaGetSymbolAddress((void**)&p_h,     g_h);
    cudaGetSymbolAddress((void**)&t_val,   g_wtval);
    cudaGetSymbolAddress((void**)&t_offat, g_wtoffat);
    cudaGetSymbolAddress((void**)&t_out,   g_wtout);
    cudaGetSymbolAddress((void**)&t_w1,    g_wt1);
    cudaGetSymbolAddress((void**)&t_w2,    g_wt2);

    const int SMEM   = 6 * TBYTES;                       // 98304
    const int SMEMLN = 3 * TBYTES + 3 * 256 * TROWB;     // 147456
    cudaFuncSetAttribute(gemm_bf, cudaFuncAttributeMaxDynamicSharedMemorySize, SMEM);
    cudaFuncSetAttribute(gemm_ln, cudaFuncAttributeMaxDynamicSharedMemorySize, SMEMLN);

    const int MY = MTOK / 128;   // 340

    // 1. srcb = bf16(src); qb = bf16(src + pos)   (K-permuted)
    prep_kernel<<<(MTOK * 256 / 4 + 255) / 256, 256>>>(src, pos, p_srcb, p_qb, MTOK * 256 / 4);

    // 2. all weight transposes in one launch (K-permuted)
    TSeg s0 = { w_val,  t_val,   256, 256,   0,   0 };
    TSeg s1 = { w_off,  t_offat, 256, 256,  64,   0 };
    TSeg s2 = { w_attn, t_offat, 256, 128, 128, 256 };
    TSeg s3 = { w_out,  t_out,   256, 256, 160,   0 };
    TSeg s4 = { w1,     t_w1,    256, 1024, 224,  0 };
    TSeg s5 = { w2,     t_w2,    1024, 256, 480,  0 };
    transpose_all<<<736, dim3(32, 8)>>>(s0, s1, s2, s3, s4, s5);

    // 3. value = srcb @ w_val + b_val (masked), bf16 out (permuted)
    gemm_bf<<<dim3(2, MY), 128, SMEM>>>(p_srcb, t_val, b_val, nullptr, mask,
                                        nullptr, nullptr, p_value, 256, 256, 0, -1, 0);
    // 4. [off | attn] = qb @ t_offat  (split epilogue, fp32 unpermuted)
    gemm_bf<<<dim3(3, MY), 128, SMEM>>>(p_qb, t_offat, b_off, b_attn, nullptr,
                                        p_off, p_attn, nullptr, 256, 256, 128, 256, 0);
    // 5. deformable sampling (permuted in/out)
    samp_kernel<<<(MTOK * NHEADS) / 8, 256>>>(p_value, p_attn, p_off, ref, p_samp);
    // 6. x = LN(src + samp @ w_out + b_out)  -> fp32 (unperm) + bf16 (perm)
    gemm_ln<<<dim3(1, MY), 256, SMEMLN>>>(p_samp, t_out, b_out, src, ln1g, ln1b, p_x, p_xb, 256);
    // 7. h = relu(xb @ w1 + b1), bf16 out (permuted)
    gemm_bf<<<dim3(8, MY), 128, SMEM>>>(p_xb, t_w1, b1, nullptr, nullptr,
                                        nullptr, nullptr, p_h, 256, 1024, 0, -1, 1);
    // 8. out = LN(x + h @ w2 + b2)  (fp32 unpermuted)
    gemm_ln<<<dim3(1, MY), 256, SMEMLN>>>(p_h, t_w2, b2, p_x, ln2g, ln2b, out, nullptr, 1024);
}

// round 17
// speedup vs baseline: 1.0974x; 1.0324x over previous
#include <cuda_runtime.h>
#include <cuda_bf16.h>
#include <cstdint>
#include <math.h>

// Problem constants (fixed by the dataset)
#define LEN    21760
#define BATCH  2
#define MTOK   (BATCH * LEN)          // 43520
#define DMODEL 256
#define DFFN   1024
#define NHEADS 8
#define LNEPS  1e-5f

typedef __nv_bfloat16 bf16;
typedef __nv_bfloat162 bf162;

// K-permutation within each 16-element group: [0,1,8,9,2,3,10,11,4,5,12,13,6,7,14,15]
__host__ __device__ __forceinline__ int permk(int k) {
    return (k & ~15) | (((k >> 1) & 3) << 2) | (((k >> 3) & 1) << 1) | (k & 1);
}
__device__ __forceinline__ int permpair(int pi) {
    return (pi & ~7) | ((pi & 3) << 1) | ((pi >> 2) & 1);
}

// ---------------------------------------------------------------------------
// Scratch (device globals — no allocation).  bf16 activations K-permuted.
// ---------------------------------------------------------------------------
__device__ bf16  g_srcb [(size_t)MTOK * DMODEL];
__device__ bf16  g_qb   [(size_t)MTOK * DMODEL];
__device__ bf16  g_value[(size_t)MTOK * DMODEL];
__device__ float g_off  [(size_t)MTOK * DMODEL];
__device__ float g_attn [(size_t)MTOK * 128];
__device__ bf16  g_samp [(size_t)MTOK * DMODEL];
__device__ float g_x    [(size_t)MTOK * DMODEL];
__device__ bf16  g_xb   [(size_t)MTOK * DMODEL];
__device__ bf16  g_h    [(size_t)MTOK * DFFN];
// transposed bf16 weights [N, K] (K-major, K permuted)
__device__ bf16 g_wtval   [256 * 256];
__device__ bf16 g_wtoffat [384 * 256];
__device__ bf16 g_wtout   [256 * 256];
__device__ bf16 g_wt1     [1024 * 256];
__device__ bf16 g_wt2     [256 * 1024];

// ---------------------------------------------------------------------------
// Helpers
// ---------------------------------------------------------------------------
__device__ __forceinline__ uint32_t smem_u32(const void* p) {
    uint32_t a;
    asm("{ .reg .u64 t; cvta.to.shared.u64 t, %1; cvt.u32.u64 %0, t; }" : "=r"(a) : "l"(p));
    return a;
}
__device__ __forceinline__ void cp_async16(uint32_t saddr, const void* gaddr) {
    asm volatile("cp.async.cg.shared.global [%0], [%1], 16;" :: "r"(saddr), "l"(gaddr));
}
__device__ __forceinline__ void cp_commit() { asm volatile("cp.async.commit_group;"); }

__device__ __forceinline__ void mma_bf16(float* d, const uint32_t* a, const uint32_t* b) {
    asm volatile(
        "mma.sync.aligned.m16n8k16.row.col.f32.bf16.bf16.f32 "
        "{%0,%1,%2,%3}, {%4,%5,%6,%7}, {%8,%9}, {%0,%1,%2,%3};"
        : "+f"(d[0]), "+f"(d[1]), "+f"(d[2]), "+f"(d[3])
        : "r"(a[0]), "r"(a[1]), "r"(a[2]), "r"(a[3]), "r"(b[0]), "r"(b[1]));
}

// Swizzled smem addressing: rows of 128B (64 bf16), 16B chunks, chunk XOR (row&3)<<1.
__device__ __forceinline__ uint32_t swz_store(int row, int c) {
    return (uint32_t)(row * 128 + ((c ^ ((row & 3) << 1)) << 4));
}
__device__ __forceinline__ uint32_t swz_frag(int r, int kk, int gc) {
    const int chunk = (kk >> 3) + (gc >> 1);
    return (uint32_t)(r * 128 + ((chunk ^ ((r & 3) << 1)) << 4) + ((gc & 1) << 3));
}

// ---------------------------------------------------------------------------
// Merged prep + weight transpose (independent preprocessing, one launch).
// Blocks [0, NBPREP): srcb = bf16(src), qb = bf16(src+pos)  (K-permuted)
// Blocks [NBPREP, NBPREP+736): transpose segments.
// ---------------------------------------------------------------------------
#define NBPREP (MTOK * 64 / 256)   // 10880

struct TSeg { const float* in; bf16* out; int K, N, start, rowOff; };

__global__ __launch_bounds__(256)
void prep_transpose(const float* __restrict__ src, const float* __restrict__ pos,
                    bf16* __restrict__ srcb, bf16* __restrict__ qb,
                    TSeg s0, TSeg s1, TSeg s2, TSeg s3, TSeg s4, TSeg s5)
{
    const int tid = threadIdx.x;
    if (blockIdx.x < NBPREP) {
        const int i = blockIdx.x * 256 + tid;
        float4 s = ((const float4*)src)[i];
        float4 p = ((const float4*)pos)[i];
        const int pi0 = permpair(2 * i);
        const int pi1 = permpair(2 * i + 1);
        ((bf162*)srcb)[pi0] = __floats2bfloat162_rn(s.x, s.y);
        ((bf162*)srcb)[pi1] = __floats2bfloat162_rn(s.z, s.w);
        ((bf162*)qb)[pi0] = __floats2bfloat162_rn(s.x + p.x, s.y + p.y);
        ((bf162*)qb)[pi1] = __floats2bfloat162_rn(s.z + p.z, s.w + p.w);
        return;
    }
    const int b = blockIdx.x - NBPREP;
    TSeg s;
    if      (b < s1.start) s = s0;
    else if (b < s2.start) s = s1;
    else if (b < s3.start) s = s2;
    else if (b < s4.start) s = s3;
    else if (b < s5.start) s = s4;
    else                   s = s5;

    const int local = b - s.start;
    const int tx_n  = s.N / 32;
    const int n0 = (local % tx_n) * 32;
    const int k0 = (local / tx_n) * 32;

    __shared__ float t[32][33];
    const int tx = tid & 31, ty = tid >> 5;
#pragma unroll
    for (int j = 0; j < 32; j += 8)
        t[ty + j][tx] = s.in[(size_t)(k0 + ty + j) * s.N + n0 + tx];
    __syncthreads();
#pragma unroll
    for (int j = 0; j < 32; j += 8)
        s.out[(size_t)(s.rowOff + n0 + ty + j) * s.K + permk(k0 + tx)] = __float2bfloat16(t[tx][ty + j]);
}

// ---------------------------------------------------------------------------
// Shared GEMM mainloop pieces (BM=BN=128, BK=64, 128 thr, warp 64x64, 3-stage)
// ---------------------------------------------------------------------------
#define TROWB 128
#define TBYTES (128 * TROWB)

#define GEMM_MAIN(APTR, BPTR, KVAL)                                               \
    float acc[4][8][4];                                                           \
    _Pragma("unroll")                                                             \
    for (int mt = 0; mt < 4; mt++)                                                \
        _Pragma("unroll")                                                         \
        for (int nt = 0; nt < 8; nt++)                                            \
            _Pragma("unroll")                                                     \
            for (int r = 0; r < 4; r++) acc[mt][nt][r] = 0.f;                     \
    const int nch = (KVAL) >> 6;                                                  \
    const int lrow = tid >> 3;                                                    \
    const int lchk = tid & 7;                                                     \
    const int lc   = lchk << 3;                                                   \
    const bf16* Ab = (APTR) + (size_t)lrow * (KVAL) + lc;                         \
    const bf16* Bb = (BPTR) + (size_t)lrow * (KVAL) + lc;                         \
    for (int pre = 0; pre < 2 && pre < nch; pre++) {                              \
        const int _k0 = pre << 6;                                                 \
        const uint32_t _abase = sA + pre * TBYTES;                                \
        const uint32_t _bbase = sB + pre * TBYTES;                                \
        _Pragma("unroll")                                                         \
        for (int it = 0; it < 8; it++) {                                          \
            const int r = lrow + it * 16;                                         \
            cp_async16(_abase + swz_store(r, lchk), Ab + (size_t)(it * 16) * (KVAL) + _k0); \
            cp_async16(_bbase + swz_store(r, lchk), Bb + (size_t)(it * 16) * (KVAL) + _k0); \
        }                                                                         \
        cp_commit();                                                              \
    }                                                                             \
    for (int i = 0; i < nch; i++) {                                               \
        if (i + 2 < nch) {                                                        \
            const int _k0 = (i + 2) << 6;                                         \
            const uint32_t _abase = sA + ((i + 2) % 3) * TBYTES;                  \
            const uint32_t _bbase = sB + ((i + 2) % 3) * TBYTES;                  \
            _Pragma("unroll")                                                     \
            for (int it = 0; it < 8; it++) {                                      \
                const int r = lrow + it * 16;                                     \
                cp_async16(_abase + swz_store(r, lchk), Ab + (size_t)(it * 16) * (KVAL) + _k0); \
                cp_async16(_bbase + swz_store(r, lchk), Bb + (size_t)(it * 16) * (KVAL) + _k0); \
            }                                                                     \
            cp_commit();                                                          \
            asm volatile("cp.async.wait_group 2;" ::: "memory");                  \
        } else if (i + 1 < nch) {                                                 \
            asm volatile("cp.async.wait_group 1;" ::: "memory");                  \
        } else {                                                                  \
            asm volatile("cp.async.wait_group 0;" ::: "memory");                  \
        }                                                                         \
        __syncthreads();                                                          \
        const uint32_t sAc = sA + (i % 3) * TBYTES;                               \
        const uint32_t sBc = sB + (i % 3) * TBYTES;                               \
        _Pragma("unroll")                                                         \
        for (int ks = 0; ks < 4; ks++) {                                          \
            const int kk = ks * 16;                                               \
            uint32_t af[4][4];                                                    \
            _Pragma("unroll")                                                     \
            for (int mt = 0; mt < 4; mt++) {                                      \
                const int r = wm * 64 + mt * 16 + gr;                             \
                uint2 a0, a1;                                                     \
                asm volatile("ld.shared.v2.b32 {%0,%1}, [%2];" : "=r"(a0.x), "=r"(a0.y) : "r"(sAc + swz_frag(r, kk, gc))); \
                asm volatile("ld.shared.v2.b32 {%0,%1}, [%2];" : "=r"(a1.x), "=r"(a1.y) : "r"(sAc + swz_frag(r + 8, kk, gc))); \
                af[mt][0] = a0.x; af[mt][1] = a1.x; af[mt][2] = a0.y; af[mt][3] = a1.y; \
            }                                                                     \
            uint32_t bfr[8][2];                                                   \
            _Pragma("unroll")                                                     \
            for (int nt = 0; nt < 8; nt++) {                                      \
                const int r = wn * 64 + nt * 8 + gr;                              \
                uint2 b0;                                                         \
                asm volatile("ld.shared.v2.b32 {%0,%1}, [%2];" : "=r"(b0.x), "=r"(b0.y) : "r"(sBc + swz_frag(r, kk, gc))); \
                bfr[nt][0] = b0.x; bfr[nt][1] = b0.y;                             \
            }                                                                     \
            _Pragma("unroll")                                                     \
            for (int mt = 0; mt < 4; mt++)                                        \
                _Pragma("unroll")                                                 \
                for (int nt = 0; nt < 8; nt++)                                    \
                    mma_bf16(acc[mt][nt], af[mt], bfr[nt]);                       \
        }                                                                         \
        __syncthreads();                                                          \
    }

// ---------------------------------------------------------------------------
// Merged value + off + attn GEMM (all depend only on prep).  K = 256.
// Grid (5, MY): bx 0-1 value (A=srcb, bf16 masked out), bx 2-3 off (A=qb,
// fp32), bx 4 attn (A=qb, fp32, N=128).
// ---------------------------------------------------------------------------
__global__ __launch_bounds__(128, 2)
void gemm_qkv(const bf16* __restrict__ srcb, const bf16* __restrict__ qb,
              const bf16* __restrict__ wval, const bf16* __restrict__ woffat,
              const float* __restrict__ b_val, const float* __restrict__ b_off,
              const float* __restrict__ b_attn, const unsigned char* __restrict__ mask,
              bf16* __restrict__ value, float* __restrict__ offo, float* __restrict__ attno)
{
    extern __shared__ bf16 sm[];
    const uint32_t sA = smem_u32(sm);
    const uint32_t sB = sA + 3 * TBYTES;

    const int tid  = threadIdx.x;
    const int wid  = tid >> 5;
    const int lane = tid & 31;
    const int gr   = lane >> 2;
    const int gc   = lane & 3;
    const int wm   = wid & 1;
    const int wn   = wid >> 1;
    const int bx   = blockIdx.x;
    const int row0 = blockIdx.y * 128;

    // path select
    const int path = (bx < 2) ? 0 : ((bx < 4) ? 1 : 2);
    const bf16* Aeff = (path == 0) ? srcb : qb;
    const bf16* Beff = (path == 0) ? wval : woffat;
    const int brow0  = (path == 0) ? bx * 128 : ((path == 1) ? (bx - 2) * 128 : 256);

    GEMM_MAIN(Aeff + (size_t)row0 * 256, Beff + (size_t)brow0 * 256, 256)

    if (path == 0) {
#pragma unroll
        for (int mt = 0; mt < 4; mt++) {
            const int r0 = row0 + wm * 64 + mt * 16 + gr;
            const bool m0 = mask[r0];
            const bool m1 = mask[r0 + 8];
#pragma unroll
            for (int nt = 0; nt < 8; nt++) {
                const int col = bx * 128 + wn * 64 + nt * 8 + gc * 2;
                const float b0 = __ldg(b_val + col);
                const float b1 = __ldg(b_val + col + 1);
                float v0 = acc[mt][nt][0] + b0, v1 = acc[mt][nt][1] + b1;
                float v2 = acc[mt][nt][2] + b0, v3 = acc[mt][nt][3] + b1;
                if (m0) { v0 = v1 = 0.f; }
                if (m1) { v2 = v3 = 0.f; }
                const int npi2 = permpair(col >> 1) * 2;
                *(bf162*)(value + (size_t)r0 * 256 + npi2)       = __floats2bfloat162_rn(v0, v1);
                *(bf162*)(value + (size_t)(r0 + 8) * 256 + npi2) = __floats2bfloat162_rn(v2, v3);
            }
        }
    } else {
        const float* biasP = (path == 1) ? b_off : b_attn;
        float* CfP = (path == 1) ? offo : attno;
        const int Nout  = (path == 1) ? 256 : 128;
        const int cbase = (path == 1) ? (bx - 2) * 128 : 0;
#pragma unroll
        for (int mt = 0; mt < 4; mt++) {
            const int r0 = row0 + wm * 64 + mt * 16 + gr;
#pragma unroll
            for (int nt = 0; nt < 8; nt++) {
                const int col = cbase + wn * 64 + nt * 8 + gc * 2;
                const float b0 = __ldg(biasP + col);
                const float b1 = __ldg(biasP + col + 1);
                *(float2*)(CfP + (size_t)r0 * Nout + col) =
                    make_float2(acc[mt][nt][0] + b0, acc[mt][nt][1] + b1);
                *(float2*)(CfP + (size_t)(r0 + 8) * Nout + col) =
                    make_float2(acc[mt][nt][2] + b0, acc[mt][nt][3] + b1);
            }
        }
    }
}

// ---------------------------------------------------------------------------
// Plain GEMM (FFN1): h = relu(xb @ w1 + b1), bf16 permuted out.
// ---------------------------------------------------------------------------
__global__ __launch_bounds__(128, 2)
void gemm_bf(const bf16* __restrict__ A, const bf16* __restrict__ BT,
             const float* __restrict__ bias, bf16* __restrict__ Cb,
             int K, int N)
{
    extern __shared__ bf16 sm[];
    const uint32_t sA = smem_u32(sm);
    const uint32_t sB = sA + 3 * TBYTES;

    const int tid  = threadIdx.x;
    const int wid  = tid >> 5;
    const int lane = tid & 31;
    const int gr   = lane >> 2;
    const int gc   = lane & 3;
    const int wm   = wid & 1;
    const int wn   = wid >> 1;
    const int row0 = blockIdx.y * 128;
    const int col0 = blockIdx.x * 128;

    GEMM_MAIN(A + (size_t)row0 * K, BT + (size_t)col0 * K, K)

#pragma unroll
    for (int mt = 0; mt < 4; mt++) {
        const int r0 = row0 + wm * 64 + mt * 16 + gr;
#pragma unroll
        for (int nt = 0; nt < 8; nt++) {
            const int col = col0 + wn * 64 + nt * 8 + gc * 2;
            const float b0 = __ldg(bias + col);
            const float b1 = __ldg(bias + col + 1);
            float v0 = fmaxf(acc[mt][nt][0] + b0, 0.f), v1 = fmaxf(acc[mt][nt][1] + b1, 0.f);
            float v2 = fmaxf(acc[mt][nt][2] + b0, 0.f), v3 = fmaxf(acc[mt][nt][3] + b1, 0.f);
            const int npi2 = permpair(col >> 1) * 2;
            *(bf162*)(Cb + (size_t)r0 * N + npi2)       = __floats2bfloat162_rn(v0, v1);
            *(bf162*)(Cb + (size_t)(r0 + 8) * N + npi2) = __floats2bfloat162_rn(v2, v3);
        }
    }
}

// ---------------------------------------------------------------------------
// GEMM + bias + residual + LayerNorm fused.  N = 256 (full row per CTA).
// BM=128, BN=256, 256 threads (8 warps 2x4), warp 64x64, 3-stage pipeline.
// ---------------------------------------------------------------------------
__global__ __launch_bounds__(256, 1)
void gemm_ln(const bf16* __restrict__ A, const bf16* __restrict__ BT,
             const float* __restrict__ bias, const float* __restrict__ res,
             const float* __restrict__ lng, const float* __restrict__ lnb,
             float* __restrict__ Of, bf16* __restrict__ Ob, int K)
{
    extern __shared__ bf16 sm[];
    const uint32_t sA = smem_u32(sm);                 // 3 x 128 rows
    const uint32_t sB = sA + 3 * TBYTES;              // 3 x 256 rows

    const int tid  = threadIdx.x;
    const int wid  = tid >> 5;
    const int lane = tid & 31;
    const int gr   = lane >> 2;
    const int gc   = lane & 3;
    const int wm   = wid & 1;
    const int wn   = wid >> 1;
    const int row0 = blockIdx.y * 128;

    float acc[4][8][4];
#pragma unroll
    for (int mt = 0; mt < 4; mt++)
#pragma unroll
        for (int nt = 0; nt < 8; nt++)
#pragma unroll
            for (int r = 0; r < 4; r++) acc[mt][nt][r] = 0.f;

    const int nch = K >> 6;
    const int lrow = tid >> 3;           // 0..31
    const int lchk = tid & 7;
    const int lc   = lchk << 3;

#define LN_LOAD(i) do {                                                            \
        const int _k0 = (i) << 6;                                                  \
        const uint32_t _ab = sA + ((i) % 3) * TBYTES;                              \
        const uint32_t _bb = sB + ((i) % 3) * (256 * TROWB);                       \
        _Pragma("unroll")                                                          \
        for (int it = 0; it < 4; it++) {                                           \
            const int r = lrow + it * 32;                                          \
            cp_async16(_ab + swz_store(r, lchk),                                   \
                       A + (size_t)(row0 + r) * K + lc + _k0);                     \
        }                                                                          \
        _Pragma("unroll")                                                          \
        for (int it = 0; it < 8; it++) {                                           \
            const int r = lrow + it * 32;                                          \
            cp_async16(_bb + swz_store(r, lchk),                                   \
                       BT + (size_t)r * K + lc + _k0);                             \
        }                                                                          \
        cp_commit();                                                               \
    } while (0)

    LN_LOAD(0);
    if (nch > 1) LN_LOAD(1);

    for (int i = 0; i < nch; i++) {
        if (i + 2 < nch) {
            LN_LOAD(i + 2);
            asm volatile("cp.async.wait_group 2;" ::: "memory");
        } else if (i + 1 < nch) {
            asm volatile("cp.async.wait_group 1;" ::: "memory");
        } else {
            asm volatile("cp.async.wait_group 0;" ::: "memory");
        }
        __syncthreads();

        const uint32_t sAc = sA + (i % 3) * TBYTES;
        const uint32_t sBc = sB + (i % 3) * (256 * TROWB);

#pragma unroll
        for (int ks = 0; ks < 4; ks++) {
            const int kk = ks * 16;
            uint32_t af[4][4];
#pragma unroll
            for (int mt = 0; mt < 4; mt++) {
                const int r = wm * 64 + mt * 16 + gr;
                uint2 a0, a1;
                asm volatile("ld.shared.v2.b32 {%0,%1}, [%2];" : "=r"(a0.x), "=r"(a0.y) : "r"(sAc + swz_frag(r, kk, gc)));
                asm volatile("ld.shared.v2.b32 {%0,%1}, [%2];" : "=r"(a1.x), "=r"(a1.y) : "r"(sAc + swz_frag(r + 8, kk, gc)));
                af[mt][0] = a0.x; af[mt][1] = a1.x; af[mt][2] = a0.y; af[mt][3] = a1.y;
            }
            uint32_t bfr[8][2];
#pragma unroll
            for (int nt = 0; nt < 8; nt++) {
                const int r = wn * 64 + nt * 8 + gr;
                uint2 b0;
                asm volatile("ld.shared.v2.b32 {%0,%1}, [%2];" : "=r"(b0.x), "=r"(b0.y) : "r"(sBc + swz_frag(r, kk, gc)));
                bfr[nt][0] = b0.x; bfr[nt][1] = b0.y;
            }
#pragma unroll
            for (int mt = 0; mt < 4; mt++)
#pragma unroll
                for (int nt = 0; nt < 8; nt++)
                    mma_bf16(acc[mt][nt], af[mt], bfr[nt]);
        }
        __syncthreads();
    }

    // ---- fused bias + residual + LayerNorm ----
    float2* sred = (float2*)sm;          // [128][4] partials

#pragma unroll
    for (int mt = 0; mt < 4; mt++) {
        const int rA = wm * 64 + mt * 16 + gr;
        const int rB = rA + 8;
        float sA2 = 0.f, qA = 0.f, sB2 = 0.f, qB = 0.f;
#pragma unroll
        for (int nt = 0; nt < 8; nt++) {
            const int col = wn * 64 + nt * 8 + gc * 2;
            const float b0 = __ldg(bias + col);
            const float b1 = __ldg(bias + col + 1);
            const float2 rs0 = *(const float2*)(res + (size_t)(row0 + rA) * 256 + col);
            const float2 rs1 = *(const float2*)(res + (size_t)(row0 + rB) * 256 + col);
            acc[mt][nt][0] += b0 + rs0.x;
            acc[mt][nt][1] += b1 + rs0.y;
            acc[mt][nt][2] += b0 + rs1.x;
            acc[mt][nt][3] += b1 + rs1.y;
            sA2 += acc[mt][nt][0] + acc[mt][nt][1];
            qA  += acc[mt][nt][0] * acc[mt][nt][0] + acc[mt][nt][1] * acc[mt][nt][1];
            sB2 += acc[mt][nt][2] + acc[mt][nt][3];
            qB  += acc[mt][nt][2] * acc[mt][nt][2] + acc[mt][nt][3] * acc[mt][nt][3];
        }
#pragma unroll
        for (int o = 1; o <= 2; o <<= 1) {
            sA2 += __shfl_xor_sync(0xffffffffu, sA2, o);
            qA  += __shfl_xor_sync(0xffffffffu, qA,  o);
            sB2 += __shfl_xor_sync(0xffffffffu, sB2, o);
            qB  += __shfl_xor_sync(0xffffffffu, qB,  o);
        }
        if (gc == 0) {
            sred[rA * 4 + wn] = make_float2(sA2, qA);
            sred[rB * 4 + wn] = make_float2(sB2, qB);
        }
    }
    __syncthreads();

#pragma unroll
    for (int mt = 0; mt < 4; mt++) {
        const int rA = wm * 64 + mt * 16 + gr;
        const int rB = rA + 8;
        float2 pA = make_float2(0.f, 0.f), pB = make_float2(0.f, 0.f);
#pragma unroll
        for (int w = 0; w < 4; w++) {
            float2 a = sred[rA * 4 + w]; pA.x += a.x; pA.y += a.y;
            float2 b = sred[rB * 4 + w]; pB.x += b.x; pB.y += b.y;
        }
        const float mA = pA.x * (1.f / 256.f);
        const float vA = fmaxf(pA.y * (1.f / 256.f) - mA * mA, 0.f);
        const float rAst = rsqrtf(vA + LNEPS);
        const float mB = pB.x * (1.f / 256.f);
        const float vB = fmaxf(pB.y * (1.f / 256.f) - mB * mB, 0.f);
        const float rBst = rsqrtf(vB + LNEPS);

#pragma unroll
        for (int nt = 0; nt < 8; nt++) {
            const int col = wn * 64 + nt * 8 + gc * 2;
            const float g0 = __ldg(lng + col),  g1 = __ldg(lng + col + 1);
            const float e0 = __ldg(lnb + col),  e1 = __ldg(lnb + col + 1);
            const float o0 = (acc[mt][nt][0] - mA) * rAst * g0 + e0;
            const float o1 = (acc[mt][nt][1] - mA) * rAst * g1 + e1;
            const float o2 = (acc[mt][nt][2] - mB) * rBst * g0 + e0;
            const float o3 = (acc[mt][nt][3] - mB) * rBst * g1 + e1;
            *(float2*)(Of + (size_t)(row0 + rA) * 256 + col) = make_float2(o0, o1);
            *(float2*)(Of + (size_t)(row0 + rB) * 256 + col) = make_float2(o2, o3);
            if (Ob) {
                const int npi2 = permpair(col >> 1) * 2;
                *(bf162*)(Ob + (size_t)(row0 + rA) * 256 + npi2) = __floats2bfloat162_rn(o0, o1);
                *(bf162*)(Ob + (size_t)(row0 + rB) * 256 + npi2) = __floats2bfloat162_rn(o2, o3);
            }
        }
    }
}

// ---------------------------------------------------------------------------
// Deformable-attention sampling.  One warp per (token, head).
// Operates in the K-permuted channel space (channel-uniform weights).
// ---------------------------------------------------------------------------
__global__ __launch_bounds__(256)
void samp_kernel(const bf16* __restrict__ value, const float* __restrict__ attn,
                 const float* __restrict__ off,  const float* __restrict__ ref,
                 bf16* __restrict__ out)
{
    const int gw   = (blockIdx.x * blockDim.x + threadIdx.x) >> 5;
    const int lane = threadIdx.x & 31;
    if (gw >= MTOK * NHEADS) return;

    const int h    = gw & 7;
    const int bl   = gw >> 3;
    const int b    = (bl >= LEN) ? 1 : 0;
    const int pgrp = lane >> 3;          // point within level
    const int cq   = lane & 7;           // channel quad

    float logit = (lane < 16) ? __ldg(attn + bl * 128 + h * 16 + lane) : -1e30f;
    float m = logit;
#pragma unroll
    for (int o = 16; o > 0; o >>= 1) m = fmaxf(m, __shfl_xor_sync(0xffffffffu, m, o));
    float e = (lane < 16) ? __expf(logit - m) : 0.f;
    float s = e;
#pragma unroll
    for (int o = 16; o > 0; o >>= 1) s += __shfl_xor_sync(0xffffffffu, s, o);
    const float wn = e / s;

    const float ov = __ldg(off + bl * 256 + h * 32 + lane);
    const float rv = (lane < 8) ? __ldg(ref + bl * 8 + lane) : 0.f;

    const int Hs[4] = {128, 64, 32, 16};
    const int Ss[4] = {0, 16384, 20480, 21504};

    float4 acc4 = make_float4(0.f, 0.f, 0.f, 0.f);
#pragma unroll
    for (int l = 0; l < 4; l++) {
        const int   Wl = Hs[l];
        const float fW = (float)Wl;
        const float rx = __shfl_sync(0xffffffffu, rv, 2 * l);
        const float ry = __shfl_sync(0xffffffffu, rv, 2 * l + 1);
        const uint2* vb = (const uint2*)(value + (size_t)(b * LEN + Ss[l]) * 256 + h * 32) + cq;

        const float ox = __shfl_sync(0xffffffffu, ov, l * 8 + pgrp * 2);
        const float oy = __shfl_sync(0xffffffffu, ov, l * 8 + pgrp * 2 + 1);
        const float aw = __shfl_sync(0xffffffffu, wn, l * 4 + pgrp);
        const float x  = fmaf(rx, fW, ox) - 0.5f;
        const float y  = fmaf(ry, fW, oy) - 0.5f;
        const float x0f = floorf(x), y0f = floorf(y);
        const float dx = x - x0f, dy = y - y0f;
        const int   x0 = (int)x0f, y0 = (int)y0f;

        float4 psum = make_float4(0.f, 0.f, 0.f, 0.f);
#pragma unroll
        for (int c = 0; c < 4; c++) {
            const int xi = x0 + (c & 1);
            const int yi = y0 + (c >> 1);
            const float cw = ((c & 1) ? dx : 1.f - dx) * ((c >> 1) ? dy : 1.f - dy);
            const bool valid = (xi >= 0) & (xi < Wl) & (yi >= 0) & (yi < Wl);
            const int xc = min(max(xi, 0), Wl - 1);
            const int yc = min(max(yi, 0), Wl - 1);
            const uint2 raw = vb[(size_t)(yc * Wl + xc) * 64];
            const float2 v0 = __bfloat1622float2(*(const bf162*)&raw.x);
            const float2 v1 = __bfloat1622float2(*(const bf162*)&raw.y);
            const float w = valid ? cw : 0.f;
            psum.x = fmaf(v0.x, w, psum.x);
            psum.y = fmaf(v0.y, w, psum.y);
            psum.z = fmaf(v1.x, w, psum.z);
            psum.w = fmaf(v1.y, w, psum.w);
        }
        acc4.x = fmaf(aw, psum.x, acc4.x);
        acc4.y = fmaf(aw, psum.y, acc4.y);
        acc4.z = fmaf(aw, psum.z, acc4.z);
        acc4.w = fmaf(aw, psum.w, acc4.w);
    }
#pragma unroll
    for (int o = 8; o <= 16; o <<= 1) {
        acc4.x += __shfl_xor_sync(0xffffffffu, acc4.x, o);
        acc4.y += __shfl_xor_sync(0xffffffffu, acc4.y, o);
        acc4.z += __shfl_xor_sync(0xffffffffu, acc4.z, o);
        acc4.w += __shfl_xor_sync(0xffffffffu, acc4.w, o);
    }
    if (pgrp == 0) {
        uint2 packed;
        bf162 p0 = __floats2bfloat162_rn(acc4.x, acc4.y);
        bf162 p1 = __floats2bfloat162_rn(acc4.z, acc4.w);
        packed.x = *(const uint32_t*)&p0;
        packed.y = *(const uint32_t*)&p1;
        ((uint2*)(out + (size_t)bl * 256 + h * 32))[cq] = packed;
    }
}

// ---------------------------------------------------------------------------
// Launch
// ---------------------------------------------------------------------------
extern "C" void kernel_launch(void* const* d_in, const int* in_sizes, int n_in,
                              void* d_out, int out_size)
{
    const float* src  = (const float*)d_in[0];
    const float* pos  = (const float*)d_in[1];
    const float* ref  = (const float*)d_in[2];
    const unsigned char* mask = (const unsigned char*)d_in[5];
    const float* w_off  = (const float*)d_in[6];
    const float* b_off  = (const float*)d_in[7];
    const float* w_attn = (const float*)d_in[8];
    const float* b_attn = (const float*)d_in[9];
    const float* w_val  = (const float*)d_in[10];
    const float* b_val  = (const float*)d_in[11];
    const float* w_out  = (const float*)d_in[12];
    const float* b_out  = (const float*)d_in[13];
    const float* ln1g   = (const float*)d_in[14];
    const float* ln1b   = (const float*)d_in[15];
    const float* w1     = (const float*)d_in[16];
    const float* b1     = (const float*)d_in[17];
    const float* w2     = (const float*)d_in[18];
    const float* b2     = (const float*)d_in[19];
    const float* ln2g   = (const float*)d_in[20];
    const float* ln2b   = (const float*)d_in[21];
    float* out = (float*)d_out;

    bf16 *p_srcb, *p_qb, *p_value, *p_samp, *p_xb, *p_h;
    float *p_off, *p_attn, *p_x;
    bf16 *t_val, *t_offat, *t_out, *t_w1, *t_w2;
    cudaGetSymbolAddress((void**)&p_srcb,  g_srcb);
    cudaGetSymbolAddress((void**)&p_qb,    g_qb);
    cudaGetSymbolAddress((void**)&p_value, g_value);
    cudaGetSymbolAddress((void**)&p_off,   g_off);
    cudaGetSymbolAddress((void**)&p_attn,  g_attn);
    cudaGetSymbolAddress((void**)&p_samp,  g_samp);
    cudaGetSymbolAddress((void**)&p_x,     g_x);
    cudaGetSymbolAddress((void**)&p_xb,    g_xb);
    cudaGetSymbolAddress((void**)&p_h,     g_h);
    cudaGetSymbolAddress((void**)&t_val,   g_wtval);
    cudaGetSymbolAddress((void**)&t_offat, g_wtoffat);
    cudaGetSymbolAddress((void**)&t_out,   g_wtout);
    cudaGetSymbolAddress((void**)&t_w1,    g_wt1);
    cudaGetSymbolAddress((void**)&t_w2,    g_wt2);

    const int SMEM   = 6 * TBYTES;                       // 98304
    const int SMEMLN = 3 * TBYTES + 3 * 256 * TROWB;     // 147456
    cudaFuncSetAttribute(gemm_qkv, cudaFuncAttributeMaxDynamicSharedMemorySize, SMEM);
    cudaFuncSetAttribute(gemm_bf,  cudaFuncAttributeMaxDynamicSharedMemorySize, SMEM);
    cudaFuncSetAttribute(gemm_ln,  cudaFuncAttributeMaxDynamicSharedMemorySize, SMEMLN);

    const int MY = MTOK / 128;   // 340

    // 1. prep (srcb/qb, K-permuted) + all weight transposes, one launch
    TSeg s0 = { w_val,  t_val,   256, 256,   0,   0 };
    TSeg s1 = { w_off,  t_offat, 256, 256,  64,   0 };
    TSeg s2 = { w_attn, t_offat, 256, 128, 128, 256 };
    TSeg s3 = { w_out,  t_out,   256, 256, 160,   0 };
    TSeg s4 = { w1,     t_w1,    256, 1024, 224,  0 };
    TSeg s5 = { w2,     t_w2,    1024, 256, 480,  0 };
    prep_transpose<<<NBPREP + 736, 256>>>(src, pos, p_srcb, p_qb, s0, s1, s2, s3, s4, s5);

    // 2. value + off + attn in one launch
    gemm_qkv<<<dim3(5, MY), 128, SMEM>>>(p_srcb, p_qb, t_val, t_offat,
                                         b_val, b_off, b_attn, mask,
                                         p_value, p_off, p_attn);
    // 3. deformable sampling (permuted in/out)
    samp_kernel<<<(MTOK * NHEADS) / 8, 256>>>(p_value, p_attn, p_off, ref, p_samp);
    // 4. x = LN(src + samp @ w_out + b_out)  -> fp32 (unperm) + bf16 (perm)
    gemm_ln<<<dim3(1, MY), 256, SMEMLN>>>(p_samp, t_out, b_out, src, ln1g, ln1b, p_x, p_xb, 256);
    // 5. h = relu(xb @ w1 + b1), bf16 permuted out
    gemm_bf<<<dim3(8, MY), 128, SMEM>>>(p_xb, t_w1, b1, p_h, 256, 1024);
    // 6. out = LN(x + h @ w2 + b2)  (fp32 unpermuted)
    gemm_ln<<<dim3(1, MY), 256, SMEMLN>>>(p_h, t_w2, b2, p_x, ln2g, ln2b, out, nullptr, 1024);
}